// round 1
// baseline (speedup 1.0000x reference)
#include <cuda_runtime.h>
#include <cuda_bf16.h>
#include <math.h>

// ----------------------------------------------------------------------------
// Problem constants
// ----------------------------------------------------------------------------
#define T_TOK 2048
#define D_MODEL 2048
#define N_Q 16
#define N_KV 4
#define HEAD 128
#define QH (N_Q*HEAD)      // 2048
#define KVH (N_KV*HEAD)    // 512
#define N_EXP 16
#define F_FF 1024
#define TOPK 4
#define SLOTS (T_TOK*TOPK) // 8192
#define EPS 1e-6f

// ----------------------------------------------------------------------------
// Scratch (device globals; no dynamic allocation allowed)
// ----------------------------------------------------------------------------
__device__ float g_hnorm[T_TOK*D_MODEL];
__device__ float g_q[T_TOK*QH];
__device__ float g_k[T_TOK*KVH];
__device__ float g_v[T_TOK*KVH];
__device__ float g_attn[T_TOK*QH];
__device__ float g_resid2[T_TOK*D_MODEL];
__device__ float g_h2[T_TOK*D_MODEL];
__device__ float g_topw[SLOTS];
__device__ int   g_topidx[SLOTS];
__device__ int   g_cnt[N_EXP];
__device__ int   g_off[N_EXP+1];
__device__ int   g_cursor[N_EXP];
__device__ int   g_tokperm[SLOTS];
__device__ int   g_slotrow[SLOTS];
__device__ float g_gu[(size_t)SLOTS*2048];
__device__ float g_gated[(size_t)SLOTS*F_FF];
__device__ float g_downo[(size_t)SLOTS*D_MODEL];

// ----------------------------------------------------------------------------
// RMSNorm over D=2048, one block per row
// ----------------------------------------------------------------------------
__global__ __launch_bounds__(256) void rmsnorm_kernel(
    const float* __restrict__ x, const float* __restrict__ w, float* __restrict__ out)
{
    const int t = blockIdx.x, tid = threadIdx.x;
    const float4* xr = (const float4*)(x + (size_t)t*D_MODEL);
    float4 a = xr[tid], b = xr[tid+256];
    float ss = a.x*a.x + a.y*a.y + a.z*a.z + a.w*a.w
             + b.x*b.x + b.y*b.y + b.z*b.z + b.w*b.w;
    #pragma unroll
    for (int off=16; off>0; off>>=1) ss += __shfl_xor_sync(0xffffffffu, ss, off);
    __shared__ float red[8];
    if ((tid&31)==0) red[tid>>5] = ss;
    __syncthreads();
    float tot = red[0]+red[1]+red[2]+red[3]+red[4]+red[5]+red[6]+red[7];
    float inv = rsqrtf(tot/(float)D_MODEL + EPS);
    const float4* wr = (const float4*)w;
    float4 wa = wr[tid], wb = wr[tid+256];
    float4* orow = (float4*)(out + (size_t)t*D_MODEL);
    orow[tid]     = make_float4(a.x*inv*wa.x, a.y*inv*wa.y, a.z*inv*wa.z, a.w*inv*wa.w);
    orow[tid+256] = make_float4(b.x*inv*wb.x, b.y*inv*wb.y, b.z*inv*wb.z, b.w*inv*wb.w);
}

// ----------------------------------------------------------------------------
// Generic SGEMM: C[M,N] = A[M,K] @ B[K,N] (+ Cadd). 64x64x16 tile, 4x4 microtile.
// M,N multiples of 64; K multiple of 16.
// ----------------------------------------------------------------------------
__global__ __launch_bounds__(256) void sgemm(
    const float* __restrict__ A, const float* __restrict__ B,
    const float* __restrict__ Cadd, float* __restrict__ C,
    int M, int N, int K)
{
    __shared__ __align__(16) float As[16][64];
    __shared__ __align__(16) float Bs[16][64];
    const int tid = threadIdx.x;
    const int bm = blockIdx.y*64, bn = blockIdx.x*64;
    const int tm = (tid>>4)<<2, tn = (tid&15)<<2;
    const int ar = tid>>2, ak = (tid&3)<<2;
    const float* Ap = A + (size_t)(bm+ar)*K + ak;
    float acc[4][4] = {};
    for (int k0=0; k0<K; k0+=16) {
        float4 av = *(const float4*)(Ap + k0);
        As[ak+0][ar]=av.x; As[ak+1][ar]=av.y; As[ak+2][ar]=av.z; As[ak+3][ar]=av.w;
        #pragma unroll
        for (int i=0;i<4;i++) {
            int idx = tid + i*256;
            int br = idx>>6, bc = idx&63;
            Bs[br][bc] = B[(size_t)(k0+br)*N + bn + bc];
        }
        __syncthreads();
        #pragma unroll
        for (int k=0;k<16;k++) {
            float4 a4 = *(const float4*)&As[k][tm];
            float4 b4 = *(const float4*)&Bs[k][tn];
            float a[4] = {a4.x,a4.y,a4.z,a4.w};
            float b[4] = {b4.x,b4.y,b4.z,b4.w};
            #pragma unroll
            for (int i=0;i<4;i++)
                #pragma unroll
                for (int j=0;j<4;j++) acc[i][j] += a[i]*b[j];
        }
        __syncthreads();
    }
    #pragma unroll
    for (int i=0;i<4;i++) {
        size_t off = (size_t)(bm+tm+i)*N + bn + tn;
        float4 v = make_float4(acc[i][0],acc[i][1],acc[i][2],acc[i][3]);
        if (Cadd) {
            float4 c4 = *(const float4*)(Cadd+off);
            v.x+=c4.x; v.y+=c4.y; v.z+=c4.z; v.w+=c4.w;
        }
        *(float4*)(C+off) = v;
    }
}

// ----------------------------------------------------------------------------
// Per-head RMSNorm (H=128) + RoPE (rot_dim=128). One block (128 thr) per row.
// x layout (T, NH, 128). In-place.
// ----------------------------------------------------------------------------
__global__ __launch_bounds__(128) void qknorm_rope(
    float* __restrict__ x, const float* __restrict__ nw,
    const float* __restrict__ cosb, const float* __restrict__ sinb, int NH)
{
    const int row = blockIdx.x;
    const int t = row / NH;
    const int tid = threadIdx.x;
    float v = x[(size_t)row*HEAD + tid];
    float ss = v*v;
    #pragma unroll
    for (int off=16; off>0; off>>=1) ss += __shfl_xor_sync(0xffffffffu, ss, off);
    __shared__ float red[4];
    __shared__ float xs[HEAD];
    if ((tid&31)==0) red[tid>>5] = ss;
    __syncthreads();
    float tot = red[0]+red[1]+red[2]+red[3];
    float inv = rsqrtf(tot/(float)HEAD + EPS);
    float xn = v*inv*nw[tid];
    xs[tid] = xn;
    __syncthreads();
    float other = xs[tid^64];
    float c = cosb[(size_t)t*HEAD + tid];
    float s = sinb[(size_t)t*HEAD + tid];
    float outv = (tid < 64) ? (xn*c - other*s) : (xn*c + other*s);
    x[(size_t)row*HEAD + tid] = outv;
}

// ----------------------------------------------------------------------------
// Causal GQA flash attention, fp32. Block = (qblock 64, head). 256 threads.
// Thread grid 16x16: rows tq*4.., key cols tk*4.., out cols tk*8..
// smem: Qs 64x129, Ks 64x129, Vs 64x132, Ps 64x64  (~113.5 KB dynamic)
// ----------------------------------------------------------------------------
#define ATTN_SMEM ((64*129 + 64*129 + 64*132 + 64*64)*4)
__global__ __launch_bounds__(256) void attn_kernel(
    const float* __restrict__ Q, const float* __restrict__ Kg,
    const float* __restrict__ Vg, float* __restrict__ O)
{
    extern __shared__ float sm[];
    float* Qs = sm;
    float* Ks = Qs + 64*129;
    float* Vs = Ks + 64*129;
    float* Ps = Vs + 64*132;
    const int h = blockIdx.y, kvh = h>>2;
    const int qb = blockIdx.x, q0 = qb*64;
    const int tid = threadIdx.x;
    const int tq = tid>>4, tk = tid&15;
    const float scale = 0.08838834764831845f; // 128^-0.5

    #pragma unroll
    for (int i=0;i<32;i++) {
        int idx = tid + i*256;
        int r = idx>>7, c = idx&127;
        Qs[r*129+c] = Q[(size_t)(q0+r)*QH + h*HEAD + c];
    }
    float m[4], l[4], o[4][8];
    #pragma unroll
    for (int i=0;i<4;i++) { m[i]=-1e30f; l[i]=0.f;
        #pragma unroll
        for (int j=0;j<8;j++) o[i][j]=0.f; }

    for (int kb=0; kb<=qb; kb++) {
        const int k0 = kb*64;
        __syncthreads();
        #pragma unroll
        for (int i=0;i<32;i++) {
            int idx = tid + i*256;
            int r = idx>>7, c = idx&127;
            Ks[r*129+c] = Kg[(size_t)(k0+r)*KVH + kvh*HEAD + c];
            Vs[r*132+c] = Vg[(size_t)(k0+r)*KVH + kvh*HEAD + c];
        }
        __syncthreads();

        float s[4][4];
        #pragma unroll
        for (int i=0;i<4;i++)
            #pragma unroll
            for (int j=0;j<4;j++) s[i][j]=0.f;
        const float* qp = Qs + (tq*4)*129;
        const float* kp = Ks + (tk*4)*129;
        #pragma unroll 4
        for (int c=0;c<128;c++) {
            float a[4], b[4];
            #pragma unroll
            for (int i=0;i<4;i++) { a[i]=qp[i*129+c]; b[i]=kp[i*129+c]; }
            #pragma unroll
            for (int i=0;i<4;i++)
                #pragma unroll
                for (int j=0;j<4;j++) s[i][j] += a[i]*b[j];
        }
        #pragma unroll
        for (int i=0;i<4;i++) {
            const int qg = q0 + tq*4 + i;
            float mx = -1e30f;
            #pragma unroll
            for (int j=0;j<4;j++) {
                int kg = k0 + tk*4 + j;
                float v = s[i][j]*scale;
                if (kg > qg) v = -1e30f;
                s[i][j] = v;
                mx = fmaxf(mx, v);
            }
            #pragma unroll
            for (int off=8; off>0; off>>=1) mx = fmaxf(mx, __shfl_xor_sync(0xffffffffu, mx, off));
            float mn = fmaxf(m[i], mx);
            float corr = expf(m[i]-mn);
            m[i] = mn;
            float rs = 0.f;
            #pragma unroll
            for (int j=0;j<4;j++) { float p = expf(s[i][j]-mn); s[i][j]=p; rs+=p; }
            #pragma unroll
            for (int off=8; off>0; off>>=1) rs += __shfl_xor_sync(0xffffffffu, rs, off);
            l[i] = l[i]*corr + rs;
            #pragma unroll
            for (int j=0;j<8;j++) o[i][j] *= corr;
            #pragma unroll
            for (int j=0;j<4;j++) Ps[(tq*4+i)*64 + tk*4 + j] = s[i][j];
        }
        __syncthreads();
        const float* pp = Ps + (tq*4)*64;
        #pragma unroll 2
        for (int kk=0;kk<64;kk++) {
            float p0=pp[kk], p1=pp[64+kk], p2=pp[128+kk], p3=pp[192+kk];
            float4 va = *(const float4*)&Vs[kk*132 + tk*8];
            float4 vb = *(const float4*)&Vs[kk*132 + tk*8 + 4];
            o[0][0]+=p0*va.x; o[0][1]+=p0*va.y; o[0][2]+=p0*va.z; o[0][3]+=p0*va.w;
            o[0][4]+=p0*vb.x; o[0][5]+=p0*vb.y; o[0][6]+=p0*vb.z; o[0][7]+=p0*vb.w;
            o[1][0]+=p1*va.x; o[1][1]+=p1*va.y; o[1][2]+=p1*va.z; o[1][3]+=p1*va.w;
            o[1][4]+=p1*vb.x; o[1][5]+=p1*vb.y; o[1][6]+=p1*vb.z; o[1][7]+=p1*vb.w;
            o[2][0]+=p2*va.x; o[2][1]+=p2*va.y; o[2][2]+=p2*va.z; o[2][3]+=p2*va.w;
            o[2][4]+=p2*vb.x; o[2][5]+=p2*vb.y; o[2][6]+=p2*vb.z; o[2][7]+=p2*vb.w;
            o[3][0]+=p3*va.x; o[3][1]+=p3*va.y; o[3][2]+=p3*va.z; o[3][3]+=p3*va.w;
            o[3][4]+=p3*vb.x; o[3][5]+=p3*vb.y; o[3][6]+=p3*vb.z; o[3][7]+=p3*vb.w;
        }
    }
    #pragma unroll
    for (int i=0;i<4;i++) {
        float invl = 1.f/l[i];
        #pragma unroll
        for (int c=0;c<8;c++)
            O[(size_t)(q0+tq*4+i)*QH + h*HEAD + tk*8 + c] = o[i][c]*invl;
    }
}

// ----------------------------------------------------------------------------
// MoE router: logits -> softmax(16) -> top-4 -> renormalize. Block per token.
// ----------------------------------------------------------------------------
__global__ __launch_bounds__(128) void router_kernel(
    const float* __restrict__ h2, const float* __restrict__ gw)
{
    const int t = blockIdx.x, tid = threadIdx.x;
    const int e = tid & 15, c = tid >> 4;
    const float* x = h2 + (size_t)t*D_MODEL;
    float acc = 0.f;
    for (int d = c*256; d < c*256+256; d++)
        acc += x[d]*gw[d*N_EXP + e];
    __shared__ float part[8][16];
    part[c][e] = acc;
    __syncthreads();
    if (tid == 0) {
        float lg[16];
        for (int ee=0; ee<16; ee++) {
            float s = 0.f;
            for (int cc=0; cc<8; cc++) s += part[cc][ee];
            lg[ee] = s;
        }
        float mx = lg[0];
        for (int ee=1; ee<16; ee++) mx = fmaxf(mx, lg[ee]);
        float pb[16]; float sum = 0.f;
        for (int ee=0; ee<16; ee++) { pb[ee] = expf(lg[ee]-mx); sum += pb[ee]; }
        float isum = 1.f/sum;
        for (int ee=0; ee<16; ee++) pb[ee] *= isum;
        bool used[16] = {};
        int idx4[4]; float w4[4]; float wsum = 0.f;
        for (int s4=0; s4<4; s4++) {
            int bi = -1; float bv = -1.f;
            for (int ee=0; ee<16; ee++)
                if (!used[ee] && pb[ee] > bv) { bv = pb[ee]; bi = ee; }
            used[bi] = true; idx4[s4] = bi; w4[s4] = bv; wsum += bv;
        }
        for (int s4=0; s4<4; s4++) {
            g_topidx[t*4+s4] = idx4[s4];
            g_topw[t*4+s4]   = w4[s4]/wsum;
            atomicAdd(&g_cnt[idx4[s4]], 1);
        }
    }
}

__global__ void zero_kernel() {
    if (threadIdx.x < N_EXP) g_cnt[threadIdx.x] = 0;
}
__global__ void offsets_kernel() {
    if (threadIdx.x == 0) {
        int acc = 0;
        for (int e=0; e<N_EXP; e++) { g_off[e] = acc; acc += g_cnt[e]; g_cursor[e] = 0; }
        g_off[N_EXP] = acc;
    }
}
__global__ __launch_bounds__(256) void scatter_kernel() {
    int idx = blockIdx.x*blockDim.x + threadIdx.x;
    if (idx >= SLOTS) return;
    int t = idx >> 2;
    int e = g_topidx[idx];
    int p = atomicAdd(&g_cursor[e], 1);
    int r = g_off[e] + p;
    g_tokperm[r] = t;
    g_slotrow[idx] = r;
}

// ----------------------------------------------------------------------------
// Grouped gate_up GEMM: gu[slot, 0:2048] = h2[tok(slot)] @ gate_up_w[e]
// ----------------------------------------------------------------------------
__global__ __launch_bounds__(256) void gateup_gemm(
    const float* __restrict__ X, const float* __restrict__ W)
{
    const int e = blockIdx.z;
    const int cnt = g_cnt[e];
    const int m0 = blockIdx.y*64;
    if (m0 >= cnt) return;
    const int base = g_off[e];
    const float* B = W + (size_t)e*2048*2048;
    __shared__ __align__(16) float As[16][64];
    __shared__ __align__(16) float Bs[16][64];
    const int tid = threadIdx.x;
    const int bn = blockIdx.x*64;
    const int tm = (tid>>4)<<2, tn = (tid&15)<<2;
    const int ar = tid>>2, ak = (tid&3)<<2;
    const int arow = m0 + ar;
    const int tok = g_tokperm[base + (arow<cnt ? arow : 0)];
    const float* Ap = X + (size_t)tok*D_MODEL + ak;
    float acc[4][4] = {};
    for (int k0=0; k0<2048; k0+=16) {
        float4 av = *(const float4*)(Ap + k0);
        As[ak+0][ar]=av.x; As[ak+1][ar]=av.y; As[ak+2][ar]=av.z; As[ak+3][ar]=av.w;
        #pragma unroll
        for (int i=0;i<4;i++) {
            int idx = tid + i*256;
            int br = idx>>6, bc = idx&63;
            Bs[br][bc] = B[(size_t)(k0+br)*2048 + bn + bc];
        }
        __syncthreads();
        #pragma unroll
        for (int k=0;k<16;k++) {
            float4 a4 = *(const float4*)&As[k][tm];
            float4 b4 = *(const float4*)&Bs[k][tn];
            float a[4] = {a4.x,a4.y,a4.z,a4.w};
            float b[4] = {b4.x,b4.y,b4.z,b4.w};
            #pragma unroll
            for (int i=0;i<4;i++)
                #pragma unroll
                for (int j=0;j<4;j++) acc[i][j] += a[i]*b[j];
        }
        __syncthreads();
    }
    #pragma unroll
    for (int i=0;i<4;i++) {
        if (m0+tm+i < cnt) {
            size_t off = (size_t)(base+m0+tm+i)*2048 + bn + tn;
            *(float4*)(g_gu + off) = make_float4(acc[i][0],acc[i][1],acc[i][2],acc[i][3]);
        }
    }
}

__global__ __launch_bounds__(256) void silu_kernel() {
    size_t idx = (size_t)blockIdx.x*blockDim.x + threadIdx.x;
    if (idx >= (size_t)SLOTS*F_FF) return;
    int r = (int)(idx >> 10), f = (int)(idx & 1023);
    float gt = g_gu[(size_t)r*2048 + f];
    float up = g_gu[(size_t)r*2048 + 1024 + f];
    g_gated[idx] = up * (gt / (1.f + expf(-gt)));
}

// ----------------------------------------------------------------------------
// Grouped down GEMM: downo[slot, 0:2048] = gated[slot, 0:1024] @ down_w[e]
// ----------------------------------------------------------------------------
__global__ __launch_bounds__(256) void down_gemm(const float* __restrict__ W)
{
    const int e = blockIdx.z;
    const int cnt = g_cnt[e];
    const int m0 = blockIdx.y*64;
    if (m0 >= cnt) return;
    const int base = g_off[e];
    const float* B = W + (size_t)e*1024*2048;
    __shared__ __align__(16) float As[16][64];
    __shared__ __align__(16) float Bs[16][64];
    const int tid = threadIdx.x;
    const int bn = blockIdx.x*64;
    const int tm = (tid>>4)<<2, tn = (tid&15)<<2;
    const int ar = tid>>2, ak = (tid&3)<<2;
    const int arow = m0 + ar;
    const float* Ap = g_gated + (size_t)(base + (arow<cnt ? arow : 0))*F_FF + ak;
    float acc[4][4] = {};
    for (int k0=0; k0<F_FF; k0+=16) {
        float4 av = *(const float4*)(Ap + k0);
        As[ak+0][ar]=av.x; As[ak+1][ar]=av.y; As[ak+2][ar]=av.z; As[ak+3][ar]=av.w;
        #pragma unroll
        for (int i=0;i<4;i++) {
            int idx = tid + i*256;
            int br = idx>>6, bc = idx&63;
            Bs[br][bc] = B[(size_t)(k0+br)*2048 + bn + bc];
        }
        __syncthreads();
        #pragma unroll
        for (int k=0;k<16;k++) {
            float4 a4 = *(const float4*)&As[k][tm];
            float4 b4 = *(const float4*)&Bs[k][tn];
            float a[4] = {a4.x,a4.y,a4.z,a4.w};
            float b[4] = {b4.x,b4.y,b4.z,b4.w};
            #pragma unroll
            for (int i=0;i<4;i++)
                #pragma unroll
                for (int j=0;j<4;j++) acc[i][j] += a[i]*b[j];
        }
        __syncthreads();
    }
    #pragma unroll
    for (int i=0;i<4;i++) {
        if (m0+tm+i < cnt) {
            size_t off = (size_t)(base+m0+tm+i)*2048 + bn + tn;
            *(float4*)(g_downo + off) = make_float4(acc[i][0],acc[i][1],acc[i][2],acc[i][3]);
        }
    }
}

// ----------------------------------------------------------------------------
// Final combine: out = resid2 + sum_slot topw * down_out[slotrow]
// ----------------------------------------------------------------------------
__global__ __launch_bounds__(256) void combine_kernel(float* __restrict__ out)
{
    size_t idx = (size_t)blockIdx.x*blockDim.x + threadIdx.x;
    if (idx >= (size_t)T_TOK*D_MODEL) return;
    int t = (int)(idx >> 11);
    int d = (int)(idx & 2047);
    float acc = g_resid2[idx];
    #pragma unroll
    for (int s=0; s<4; s++) {
        int row = g_slotrow[t*4+s];
        acc += g_topw[t*4+s] * g_downo[(size_t)row*2048 + d];
    }
    out[idx] = acc;
}

// ----------------------------------------------------------------------------
// Launcher
// ----------------------------------------------------------------------------
extern "C" void kernel_launch(void* const* d_in, const int* in_sizes, int n_in,
                              void* d_out, int out_size)
{
    const float* hidden = (const float*)d_in[0];
    const float* cosb   = (const float*)d_in[1];
    const float* sinb   = (const float*)d_in[2];
    // d_in[3] attention_mask: exactly causal -1e9; applied analytically in-kernel
    const float* iln    = (const float*)d_in[4];
    const float* pln    = (const float*)d_in[5];
    const float* qw     = (const float*)d_in[6];
    const float* kw     = (const float*)d_in[7];
    const float* vw     = (const float*)d_in[8];
    const float* ow     = (const float*)d_in[9];
    const float* qnw    = (const float*)d_in[10];
    const float* knw    = (const float*)d_in[11];
    const float* gw     = (const float*)d_in[12];
    const float* guw    = (const float*)d_in[13];
    const float* dww    = (const float*)d_in[14];
    float* out = (float*)d_out;

    cudaFuncSetAttribute(attn_kernel, cudaFuncAttributeMaxDynamicSharedMemorySize, ATTN_SMEM);

    void* p;
    cudaGetSymbolAddress(&p, g_hnorm);  float* hnorm  = (float*)p;
    cudaGetSymbolAddress(&p, g_q);      float* qbuf   = (float*)p;
    cudaGetSymbolAddress(&p, g_k);      float* kbuf   = (float*)p;
    cudaGetSymbolAddress(&p, g_v);      float* vbuf   = (float*)p;
    cudaGetSymbolAddress(&p, g_attn);   float* abuf   = (float*)p;
    cudaGetSymbolAddress(&p, g_resid2); float* resid2 = (float*)p;
    cudaGetSymbolAddress(&p, g_h2);     float* h2buf  = (float*)p;

    // 1) input RMSNorm
    rmsnorm_kernel<<<T_TOK, 256>>>(hidden, iln, hnorm);
    // 2) QKV projections
    sgemm<<<dim3(QH/64,  T_TOK/64), 256>>>(hnorm, qw, nullptr, qbuf, T_TOK, QH,  D_MODEL);
    sgemm<<<dim3(KVH/64, T_TOK/64), 256>>>(hnorm, kw, nullptr, kbuf, T_TOK, KVH, D_MODEL);
    sgemm<<<dim3(KVH/64, T_TOK/64), 256>>>(hnorm, vw, nullptr, vbuf, T_TOK, KVH, D_MODEL);
    // 3) per-head norm + RoPE
    qknorm_rope<<<T_TOK*N_Q,  128>>>(qbuf, qnw, cosb, sinb, N_Q);
    qknorm_rope<<<T_TOK*N_KV, 128>>>(kbuf, knw, cosb, sinb, N_KV);
    // 4) causal GQA attention
    attn_kernel<<<dim3(T_TOK/64, N_Q), 256, ATTN_SMEM>>>(qbuf, kbuf, vbuf, abuf);
    // 5) O projection + residual add
    sgemm<<<dim3(D_MODEL/64, T_TOK/64), 256>>>(abuf, ow, hidden, resid2, T_TOK, D_MODEL, QH);
    // 6) post RMSNorm
    rmsnorm_kernel<<<T_TOK, 256>>>(resid2, pln, h2buf);
    // 7) MoE routing + expert permutation
    zero_kernel<<<1, 32>>>();
    router_kernel<<<T_TOK, 128>>>(h2buf, gw);
    offsets_kernel<<<1, 1>>>();
    scatter_kernel<<<SLOTS/256, 256>>>();
    // 8) sparse expert GEMMs
    gateup_gemm<<<dim3(2048/64, T_TOK/64, N_EXP), 256>>>(h2buf, guw);
    silu_kernel<<<(SLOTS*F_FF)/256, 256>>>();
    down_gemm<<<dim3(D_MODEL/64, T_TOK/64, N_EXP), 256>>>(dww);
    // 9) weighted combine + residual
    combine_kernel<<<(T_TOK*D_MODEL)/256, 256>>>(out);
}

// round 3
// speedup vs baseline: 3.3471x; 3.3471x over previous
#include <cuda_runtime.h>
#include <cuda_bf16.h>
#include <math.h>
#include <stdint.h>

// ----------------------------------------------------------------------------
// Problem constants
// ----------------------------------------------------------------------------
#define T_TOK 2048
#define D_MODEL 2048
#define N_Q 16
#define N_KV 4
#define HEAD 128
#define QH (N_Q*HEAD)      // 2048
#define KVH (N_KV*HEAD)    // 512
#define N_EXP 16
#define F_FF 1024
#define TOPK 4
#define SLOTS (T_TOK*TOPK) // 8192
#define EPS 1e-6f

// ----------------------------------------------------------------------------
// Scratch (device globals; no dynamic allocation allowed)
// ----------------------------------------------------------------------------
__device__ float g_hnorm[T_TOK*D_MODEL];
__device__ float g_q[T_TOK*QH];
__device__ float g_k[T_TOK*KVH];
__device__ float g_v[T_TOK*KVH];
__device__ float g_attn[T_TOK*QH];
__device__ float g_resid2[T_TOK*D_MODEL];
__device__ float g_h2[T_TOK*D_MODEL];
__device__ float g_topw[SLOTS];
__device__ int   g_topidx[SLOTS];
__device__ int   g_cnt[N_EXP];
__device__ int   g_off[N_EXP+1];
__device__ int   g_cursor[N_EXP];
__device__ int   g_tokperm[SLOTS];
__device__ int   g_slotrow[SLOTS];
__device__ float g_gu[(size_t)SLOTS*2048];
__device__ float g_gated[(size_t)SLOTS*F_FF];
__device__ float g_downo[(size_t)SLOTS*D_MODEL];

// ----------------------------------------------------------------------------
// tf32 helpers (baseline PTX; no 'a'-features — compute_103-safe)
// ----------------------------------------------------------------------------
__device__ __forceinline__ uint32_t f2tf(float f) {
    uint32_t u;
    asm("cvt.rna.tf32.f32 %0, %1;" : "=r"(u) : "f"(f));
    return u;
}

#define MMA_TF32(cc, aa, bb) \
    asm volatile("mma.sync.aligned.m16n8k8.row.col.f32.tf32.tf32.f32 " \
        "{%0,%1,%2,%3}, {%4,%5,%6,%7}, {%8,%9}, {%0,%1,%2,%3};" \
        : "+f"(cc[0]), "+f"(cc[1]), "+f"(cc[2]), "+f"(cc[3]) \
        : "r"(aa[0]), "r"(aa[1]), "r"(aa[2]), "r"(aa[3]), "r"(bb[0]), "r"(bb[1]))

// A tile smem: [row 0..127][k 0..31], float idx:
#define SWZA(r, c) ((r)*32 + (((((c)>>2) ^ ((r)&7))) << 2) + ((c)&3))
// B tile smem: [k 0..31][n 0..127], float idx:
#define SWZB(k, n) ((k)*128 + (((((n)>>2) ^ (((k)&3)<<1))) << 2) + ((n)&3))

// ----------------------------------------------------------------------------
// tf32 tensor-core GEMM: D[M,N] = A[M,K] @ B[K,N] (+Cadd)
// Block tile 128x128x32, 256 threads, 8 warps (warp tile 64x32), double-buffer.
// MODE 0: plain.  MODE 1: MoE gate_up (rows via g_tokperm).  MODE 2: MoE down.
// ----------------------------------------------------------------------------
#define GBM 128
#define GBN 128
#define GBK 32
#define GEMM_SMEM (2*(4096+4096)*4)   // 65536

#define LOAD_G(IT) do {                                                        \
    const int k0_ = (IT)*GBK;                                                  \
    _Pragma("unroll")                                                          \
    for (int i_=0;i_<4;i_++) aReg[i_] = *(const float4*)(arp[i_] + k0_);       \
    const float* bp_ = Bsrc + (size_t)k0_*ldb + bn + bn4*4;                    \
    _Pragma("unroll")                                                          \
    for (int i_=0;i_<4;i_++)                                                   \
        bReg[i_] = *(const float4*)(bp_ + (size_t)(bk + i_*8)*ldb);            \
} while(0)

#define STAGE_S(S) do {                                                        \
    uint32_t* as_ = Ash + (S)*4096;                                            \
    uint32_t* bs_ = Bsh + (S)*4096;                                            \
    _Pragma("unroll")                                                          \
    for (int i_=0;i_<4;i_++) {                                                 \
        uint4 v_;                                                              \
        v_.x=f2tf(aReg[i_].x); v_.y=f2tf(aReg[i_].y);                          \
        v_.z=f2tf(aReg[i_].z); v_.w=f2tf(aReg[i_].w);                          \
        *(uint4*)(as_ + aoff[i_]) = v_;                                        \
    }                                                                          \
    _Pragma("unroll")                                                          \
    for (int i_=0;i_<4;i_++) {                                                 \
        int kk_ = bk + i_*8;                                                   \
        uint4 v_;                                                              \
        v_.x=f2tf(bReg[i_].x); v_.y=f2tf(bReg[i_].y);                          \
        v_.z=f2tf(bReg[i_].z); v_.w=f2tf(bReg[i_].w);                          \
        *(uint4*)(bs_ + kk_*128 + (((bn4 ^ ((kk_&3)<<1)))<<2)) = v_;           \
    }                                                                          \
} while(0)

#define COMPUTE_S(S) do {                                                      \
    const uint32_t* as_ = Ash + (S)*4096;                                      \
    const uint32_t* bs_ = Bsh + (S)*4096;                                      \
    _Pragma("unroll")                                                          \
    for (int ks_=0; ks_<4; ks_++) {                                            \
        const int k0_ = ks_*8;                                                 \
        uint32_t af[4][4], bf[4][2];                                           \
        _Pragma("unroll")                                                      \
        for (int mt_=0; mt_<4; mt_++) {                                        \
            int r_ = wm + mt_*16 + (lane>>2);                                  \
            af[mt_][0] = as_[SWZA(r_,   k0_+(lane&3))];                        \
            af[mt_][1] = as_[SWZA(r_+8, k0_+(lane&3))];                        \
            af[mt_][2] = as_[SWZA(r_,   k0_+4+(lane&3))];                      \
            af[mt_][3] = as_[SWZA(r_+8, k0_+4+(lane&3))];                      \
        }                                                                      \
        _Pragma("unroll")                                                      \
        for (int nt_=0; nt_<4; nt_++) {                                        \
            int n_ = wn + nt_*8 + (lane>>2);                                   \
            bf[nt_][0] = bs_[SWZB(k0_+(lane&3),   n_)];                        \
            bf[nt_][1] = bs_[SWZB(k0_+4+(lane&3), n_)];                        \
        }                                                                      \
        _Pragma("unroll")                                                      \
        for (int mt_=0; mt_<4; mt_++)                                          \
            _Pragma("unroll")                                                  \
            for (int nt_=0; nt_<4; nt_++)                                      \
                MMA_TF32(c[mt_][nt_], af[mt_], bf[nt_]);                       \
    }                                                                          \
} while(0)

template<int MODE>
__global__ __launch_bounds__(256)
void mma_gemm(const float* __restrict__ A, const float* __restrict__ B, int ldb,
              const float* __restrict__ Cadd, float* __restrict__ C, int ldc,
              int K)
{
    extern __shared__ uint32_t smu[];
    uint32_t* Ash = smu;            // [2][4096]
    uint32_t* Bsh = smu + 8192;     // [2][4096]

    const int tid  = threadIdx.x;
    const int lane = tid & 31;
    const int w    = tid >> 5;
    const int wm   = (w & 1) * 64;
    const int wn   = (w >> 1) * 32;
    const int bn   = blockIdx.x * GBN;
    const int m0   = blockIdx.y * GBM;

    int cnt_rows = GBM;
    int base = 0;
    size_t cBase;
    const float* Bsrc = B;
    if (MODE == 0) {
        cBase = (size_t)m0 * ldc;
    } else {
        const int e = blockIdx.z;
        const int cnt = g_cnt[e];
        if (m0 >= cnt) return;
        base = g_off[e];
        cnt_rows = min(GBM, cnt - m0);
        Bsrc = B + (size_t)e * (size_t)K * (size_t)ldb;
        cBase = (size_t)(base + m0) * ldc;
    }

    // A staging: 4 rows per thread (rows tid>>3 + i*32), float4 col tid&7
    const int ac4 = tid & 7;
    const float* arp[4];
    int aoff[4];
    #pragma unroll
    for (int i = 0; i < 4; i++) {
        int row = (tid >> 3) + i * 32;
        int rl = min(row, cnt_rows - 1);
        size_t gr;
        if (MODE == 0)      gr = (size_t)(m0 + row);
        else if (MODE == 1) gr = (size_t)g_tokperm[base + m0 + rl];
        else                gr = (size_t)(base + m0 + rl);
        arp[i] = A + gr * (size_t)K + ac4 * 4;
        aoff[i] = row * 32 + ((ac4 ^ (row & 7)) << 2);
    }
    // B staging: warp w covers k row bk=w (+i*8), lane covers n group
    const int bk  = tid >> 5;
    const int bn4 = tid & 31;

    float4 aReg[4], bReg[4];
    float c[4][4][4] = {};

    const int nIter = K / GBK;
    LOAD_G(0);
    STAGE_S(0);
    __syncthreads();
    for (int it = 0; it < nIter; it++) {
        const int cur = it & 1;
        if (it + 1 < nIter) LOAD_G(it + 1);
        COMPUTE_S(cur);
        __syncthreads();
        if (it + 1 < nIter) {
            STAGE_S(cur ^ 1);
            __syncthreads();
        }
    }

    // Epilogue
    #pragma unroll
    for (int mt = 0; mt < 4; mt++) {
        #pragma unroll
        for (int h = 0; h < 2; h++) {
            int r = wm + mt * 16 + (lane >> 2) + h * 8;
            if (r < cnt_rows) {
                float* dst = C + cBase + (size_t)r * ldc + bn;
                const float* ad = Cadd ? (Cadd + cBase + (size_t)r * ldc + bn)
                                       : (const float*)0;
                #pragma unroll
                for (int nt = 0; nt < 4; nt++) {
                    int col = wn + nt * 8 + ((lane & 3) << 1);
                    float v0 = c[mt][nt][h * 2 + 0];
                    float v1 = c[mt][nt][h * 2 + 1];
                    if (ad) { v0 += ad[col]; v1 += ad[col + 1]; }
                    dst[col]     = v0;
                    dst[col + 1] = v1;
                }
            }
        }
    }
}

// ----------------------------------------------------------------------------
// RMSNorm over D=2048, one block per row
// ----------------------------------------------------------------------------
__global__ __launch_bounds__(256) void rmsnorm_kernel(
    const float* __restrict__ x, const float* __restrict__ w, float* __restrict__ out)
{
    const int t = blockIdx.x, tid = threadIdx.x;
    const float4* xr = (const float4*)(x + (size_t)t*D_MODEL);
    float4 a = xr[tid], b = xr[tid+256];
    float ss = a.x*a.x + a.y*a.y + a.z*a.z + a.w*a.w
             + b.x*b.x + b.y*b.y + b.z*b.z + b.w*b.w;
    #pragma unroll
    for (int off=16; off>0; off>>=1) ss += __shfl_xor_sync(0xffffffffu, ss, off);
    __shared__ float red[8];
    if ((tid&31)==0) red[tid>>5] = ss;
    __syncthreads();
    float tot = red[0]+red[1]+red[2]+red[3]+red[4]+red[5]+red[6]+red[7];
    float inv = rsqrtf(tot/(float)D_MODEL + EPS);
    const float4* wr = (const float4*)w;
    float4 wa = wr[tid], wb = wr[tid+256];
    float4* orow = (float4*)(out + (size_t)t*D_MODEL);
    orow[tid]     = make_float4(a.x*inv*wa.x, a.y*inv*wa.y, a.z*inv*wa.z, a.w*inv*wa.w);
    orow[tid+256] = make_float4(b.x*inv*wb.x, b.y*inv*wb.y, b.z*inv*wb.z, b.w*inv*wb.w);
}

// ----------------------------------------------------------------------------
// Per-head RMSNorm (H=128) + RoPE. One block (128 thr) per row.
// ----------------------------------------------------------------------------
__global__ __launch_bounds__(128) void qknorm_rope(
    float* __restrict__ x, const float* __restrict__ nw,
    const float* __restrict__ cosb, const float* __restrict__ sinb, int NH)
{
    const int row = blockIdx.x;
    const int t = row / NH;
    const int tid = threadIdx.x;
    float v = x[(size_t)row*HEAD + tid];
    float ss = v*v;
    #pragma unroll
    for (int off=16; off>0; off>>=1) ss += __shfl_xor_sync(0xffffffffu, ss, off);
    __shared__ float red[4];
    __shared__ float xs[HEAD];
    if ((tid&31)==0) red[tid>>5] = ss;
    __syncthreads();
    float tot = red[0]+red[1]+red[2]+red[3];
    float inv = rsqrtf(tot/(float)HEAD + EPS);
    float xn = v*inv*nw[tid];
    xs[tid] = xn;
    __syncthreads();
    float other = xs[tid^64];
    float c = cosb[(size_t)t*HEAD + tid];
    float s = sinb[(size_t)t*HEAD + tid];
    float outv = (tid < 64) ? (xn*c - other*s) : (xn*c + other*s);
    x[(size_t)row*HEAD + tid] = outv;
}

// ----------------------------------------------------------------------------
// Causal GQA flash attention, fp32
// ----------------------------------------------------------------------------
#define ATTN_SMEM ((64*129 + 64*129 + 64*132 + 64*64)*4)
__global__ __launch_bounds__(256) void attn_kernel(
    const float* __restrict__ Q, const float* __restrict__ Kg,
    const float* __restrict__ Vg, float* __restrict__ O)
{
    extern __shared__ float smf[];
    float* Qs = smf;
    float* Ks = Qs + 64*129;
    float* Vs = Ks + 64*129;
    float* Ps = Vs + 64*132;
    const int h = blockIdx.y, kvh = h>>2;
    const int qb = blockIdx.x, q0 = qb*64;
    const int tid = threadIdx.x;
    const int tq = tid>>4, tk = tid&15;
    const float scale = 0.08838834764831845f;

    #pragma unroll
    for (int i=0;i<32;i++) {
        int idx = tid + i*256;
        int r = idx>>7, c = idx&127;
        Qs[r*129+c] = Q[(size_t)(q0+r)*QH + h*HEAD + c];
    }
    float m[4], l[4], o[4][8];
    #pragma unroll
    for (int i=0;i<4;i++) { m[i]=-1e30f; l[i]=0.f;
        #pragma unroll
        for (int j=0;j<8;j++) o[i][j]=0.f; }

    for (int kb=0; kb<=qb; kb++) {
        const int k0 = kb*64;
        __syncthreads();
        #pragma unroll
        for (int i=0;i<32;i++) {
            int idx = tid + i*256;
            int r = idx>>7, c = idx&127;
            Ks[r*129+c] = Kg[(size_t)(k0+r)*KVH + kvh*HEAD + c];
            Vs[r*132+c] = Vg[(size_t)(k0+r)*KVH + kvh*HEAD + c];
        }
        __syncthreads();

        float s[4][4];
        #pragma unroll
        for (int i=0;i<4;i++)
            #pragma unroll
            for (int j=0;j<4;j++) s[i][j]=0.f;
        const float* qp = Qs + (tq*4)*129;
        const float* kp = Ks + (tk*4)*129;
        #pragma unroll 4
        for (int c=0;c<128;c++) {
            float a[4], b[4];
            #pragma unroll
            for (int i=0;i<4;i++) { a[i]=qp[i*129+c]; b[i]=kp[i*129+c]; }
            #pragma unroll
            for (int i=0;i<4;i++)
                #pragma unroll
                for (int j=0;j<4;j++) s[i][j] += a[i]*b[j];
        }
        #pragma unroll
        for (int i=0;i<4;i++) {
            const int qg = q0 + tq*4 + i;
            float mx = -1e30f;
            #pragma unroll
            for (int j=0;j<4;j++) {
                int kg = k0 + tk*4 + j;
                float v = s[i][j]*scale;
                if (kg > qg) v = -1e30f;
                s[i][j] = v;
                mx = fmaxf(mx, v);
            }
            #pragma unroll
            for (int off=8; off>0; off>>=1) mx = fmaxf(mx, __shfl_xor_sync(0xffffffffu, mx, off));
            float mn = fmaxf(m[i], mx);
            float corr = expf(m[i]-mn);
            m[i] = mn;
            float rs = 0.f;
            #pragma unroll
            for (int j=0;j<4;j++) { float p = expf(s[i][j]-mn); s[i][j]=p; rs+=p; }
            #pragma unroll
            for (int off=8; off>0; off>>=1) rs += __shfl_xor_sync(0xffffffffu, rs, off);
            l[i] = l[i]*corr + rs;
            #pragma unroll
            for (int j=0;j<8;j++) o[i][j] *= corr;
            #pragma unroll
            for (int j=0;j<4;j++) Ps[(tq*4+i)*64 + tk*4 + j] = s[i][j];
        }
        __syncthreads();
        const float* pp = Ps + (tq*4)*64;
        #pragma unroll 2
        for (int kk=0;kk<64;kk++) {
            float p0=pp[kk], p1=pp[64+kk], p2=pp[128+kk], p3=pp[192+kk];
            float4 va = *(const float4*)&Vs[kk*132 + tk*8];
            float4 vb = *(const float4*)&Vs[kk*132 + tk*8 + 4];
            o[0][0]+=p0*va.x; o[0][1]+=p0*va.y; o[0][2]+=p0*va.z; o[0][3]+=p0*va.w;
            o[0][4]+=p0*vb.x; o[0][5]+=p0*vb.y; o[0][6]+=p0*vb.z; o[0][7]+=p0*vb.w;
            o[1][0]+=p1*va.x; o[1][1]+=p1*va.y; o[1][2]+=p1*va.z; o[1][3]+=p1*va.w;
            o[1][4]+=p1*vb.x; o[1][5]+=p1*vb.y; o[1][6]+=p1*vb.z; o[1][7]+=p1*vb.w;
            o[2][0]+=p2*va.x; o[2][1]+=p2*va.y; o[2][2]+=p2*va.z; o[2][3]+=p2*va.w;
            o[2][4]+=p2*vb.x; o[2][5]+=p2*vb.y; o[2][6]+=p2*vb.z; o[2][7]+=p2*vb.w;
            o[3][0]+=p3*va.x; o[3][1]+=p3*va.y; o[3][2]+=p3*va.z; o[3][3]+=p3*va.w;
            o[3][4]+=p3*vb.x; o[3][5]+=p3*vb.y; o[3][6]+=p3*vb.z; o[3][7]+=p3*vb.w;
        }
    }
    #pragma unroll
    for (int i=0;i<4;i++) {
        float invl = 1.f/l[i];
        #pragma unroll
        for (int c=0;c<8;c++)
            O[(size_t)(q0+tq*4+i)*QH + h*HEAD + tk*8 + c] = o[i][c]*invl;
    }
}

// ----------------------------------------------------------------------------
// MoE router + permutation machinery
// ----------------------------------------------------------------------------
__global__ __launch_bounds__(128) void router_kernel(
    const float* __restrict__ h2, const float* __restrict__ gw)
{
    const int t = blockIdx.x, tid = threadIdx.x;
    const int e = tid & 15, c = tid >> 4;
    const float* x = h2 + (size_t)t*D_MODEL;
    float acc = 0.f;
    for (int d = c*256; d < c*256+256; d++)
        acc += x[d]*gw[d*N_EXP + e];
    __shared__ float part[8][16];
    part[c][e] = acc;
    __syncthreads();
    if (tid == 0) {
        float lg[16];
        for (int ee=0; ee<16; ee++) {
            float s = 0.f;
            for (int cc=0; cc<8; cc++) s += part[cc][ee];
            lg[ee] = s;
        }
        float mx = lg[0];
        for (int ee=1; ee<16; ee++) mx = fmaxf(mx, lg[ee]);
        float pb[16]; float sum = 0.f;
        for (int ee=0; ee<16; ee++) { pb[ee] = expf(lg[ee]-mx); sum += pb[ee]; }
        float isum = 1.f/sum;
        for (int ee=0; ee<16; ee++) pb[ee] *= isum;
        bool used[16] = {};
        int idx4[4]; float w4[4]; float wsum = 0.f;
        for (int s4=0; s4<4; s4++) {
            int bi = -1; float bv = -1.f;
            for (int ee=0; ee<16; ee++)
                if (!used[ee] && pb[ee] > bv) { bv = pb[ee]; bi = ee; }
            used[bi] = true; idx4[s4] = bi; w4[s4] = bv; wsum += bv;
        }
        for (int s4=0; s4<4; s4++) {
            g_topidx[t*4+s4] = idx4[s4];
            g_topw[t*4+s4]   = w4[s4]/wsum;
            atomicAdd(&g_cnt[idx4[s4]], 1);
        }
    }
}

__global__ void zero_kernel() {
    if (threadIdx.x < N_EXP) g_cnt[threadIdx.x] = 0;
}
__global__ void offsets_kernel() {
    if (threadIdx.x == 0) {
        int acc = 0;
        for (int e=0; e<N_EXP; e++) { g_off[e] = acc; acc += g_cnt[e]; g_cursor[e] = 0; }
        g_off[N_EXP] = acc;
    }
}
__global__ __launch_bounds__(256) void scatter_kernel() {
    int idx = blockIdx.x*blockDim.x + threadIdx.x;
    if (idx >= SLOTS) return;
    int t = idx >> 2;
    int e = g_topidx[idx];
    int p = atomicAdd(&g_cursor[e], 1);
    int r = g_off[e] + p;
    g_tokperm[r] = t;
    g_slotrow[idx] = r;
}

__global__ __launch_bounds__(256) void silu_kernel() {
    size_t idx = (size_t)blockIdx.x*blockDim.x + threadIdx.x;
    if (idx >= (size_t)SLOTS*F_FF) return;
    int r = (int)(idx >> 10), f = (int)(idx & 1023);
    float gt = g_gu[(size_t)r*2048 + f];
    float up = g_gu[(size_t)r*2048 + 1024 + f];
    g_gated[idx] = up * (gt / (1.f + expf(-gt)));
}

__global__ __launch_bounds__(256) void combine_kernel(float* __restrict__ out)
{
    size_t idx = (size_t)blockIdx.x*blockDim.x + threadIdx.x;
    if (idx >= (size_t)T_TOK*D_MODEL) return;
    int t = (int)(idx >> 11);
    int d = (int)(idx & 2047);
    float acc = g_resid2[idx];
    #pragma unroll
    for (int s=0; s<4; s++) {
        int row = g_slotrow[t*4+s];
        acc += g_topw[t*4+s] * g_downo[(size_t)row*2048 + d];
    }
    out[idx] = acc;
}

// ----------------------------------------------------------------------------
// Launcher
// ----------------------------------------------------------------------------
extern "C" void kernel_launch(void* const* d_in, const int* in_sizes, int n_in,
                              void* d_out, int out_size)
{
    const float* hidden = (const float*)d_in[0];
    const float* cosb   = (const float*)d_in[1];
    const float* sinb   = (const float*)d_in[2];
    // d_in[3] attention_mask: exactly causal; applied analytically in-kernel
    const float* iln    = (const float*)d_in[4];
    const float* pln    = (const float*)d_in[5];
    const float* qw     = (const float*)d_in[6];
    const float* kw     = (const float*)d_in[7];
    const float* vw     = (const float*)d_in[8];
    const float* ow     = (const float*)d_in[9];
    const float* qnw    = (const float*)d_in[10];
    const float* knw    = (const float*)d_in[11];
    const float* gw     = (const float*)d_in[12];
    const float* guw    = (const float*)d_in[13];
    const float* dww    = (const float*)d_in[14];
    float* out = (float*)d_out;

    cudaFuncSetAttribute(attn_kernel,  cudaFuncAttributeMaxDynamicSharedMemorySize, ATTN_SMEM);
    cudaFuncSetAttribute(mma_gemm<0>,  cudaFuncAttributeMaxDynamicSharedMemorySize, GEMM_SMEM);
    cudaFuncSetAttribute(mma_gemm<1>,  cudaFuncAttributeMaxDynamicSharedMemorySize, GEMM_SMEM);
    cudaFuncSetAttribute(mma_gemm<2>,  cudaFuncAttributeMaxDynamicSharedMemorySize, GEMM_SMEM);

    void* p;
    cudaGetSymbolAddress(&p, g_hnorm);  float* hnorm  = (float*)p;
    cudaGetSymbolAddress(&p, g_q);      float* qbuf   = (float*)p;
    cudaGetSymbolAddress(&p, g_k);      float* kbuf   = (float*)p;
    cudaGetSymbolAddress(&p, g_v);      float* vbuf   = (float*)p;
    cudaGetSymbolAddress(&p, g_attn);   float* abuf   = (float*)p;
    cudaGetSymbolAddress(&p, g_resid2); float* resid2 = (float*)p;
    cudaGetSymbolAddress(&p, g_h2);     float* h2buf  = (float*)p;
    cudaGetSymbolAddress(&p, g_gu);     float* gubuf  = (float*)p;
    cudaGetSymbolAddress(&p, g_gated);  float* gtbuf  = (float*)p;
    cudaGetSymbolAddress(&p, g_downo);  float* dobuf  = (float*)p;

    // 1) input RMSNorm
    rmsnorm_kernel<<<T_TOK, 256>>>(hidden, iln, hnorm);
    // 2) QKV projections (tf32 mma.sync)
    mma_gemm<0><<<dim3(QH/128,  T_TOK/128), 256, GEMM_SMEM>>>(hnorm, qw, QH,  nullptr, qbuf, QH,  D_MODEL);
    mma_gemm<0><<<dim3(KVH/128, T_TOK/128), 256, GEMM_SMEM>>>(hnorm, kw, KVH, nullptr, kbuf, KVH, D_MODEL);
    mma_gemm<0><<<dim3(KVH/128, T_TOK/128), 256, GEMM_SMEM>>>(hnorm, vw, KVH, nullptr, vbuf, KVH, D_MODEL);
    // 3) per-head norm + RoPE
    qknorm_rope<<<T_TOK*N_Q,  128>>>(qbuf, qnw, cosb, sinb, N_Q);
    qknorm_rope<<<T_TOK*N_KV, 128>>>(kbuf, knw, cosb, sinb, N_KV);
    // 4) causal GQA attention (fp32)
    attn_kernel<<<dim3(T_TOK/64, N_Q), 256, ATTN_SMEM>>>(qbuf, kbuf, vbuf, abuf);
    // 5) O projection + residual add
    mma_gemm<0><<<dim3(D_MODEL/128, T_TOK/128), 256, GEMM_SMEM>>>(abuf, ow, D_MODEL, hidden, resid2, D_MODEL, QH);
    // 6) post RMSNorm
    rmsnorm_kernel<<<T_TOK, 256>>>(resid2, pln, h2buf);
    // 7) MoE routing + expert permutation
    zero_kernel<<<1, 32>>>();
    router_kernel<<<T_TOK, 128>>>(h2buf, gw);
    offsets_kernel<<<1, 1>>>();
    scatter_kernel<<<SLOTS/256, 256>>>();
    // 8) sparse expert GEMMs (tf32 mma.sync; max 2048 rows per expert)
    mma_gemm<1><<<dim3(2048/128, T_TOK/128, N_EXP), 256, GEMM_SMEM>>>(h2buf, guw, 2048, nullptr, gubuf, 2048, 2048);
    silu_kernel<<<(SLOTS*F_FF)/256, 256>>>();
    mma_gemm<2><<<dim3(D_MODEL/128, T_TOK/128, N_EXP), 256, GEMM_SMEM>>>(gtbuf, dww, 2048, nullptr, dobuf, 2048, 1024);
    // 9) weighted combine + residual
    combine_kernel<<<(T_TOK*D_MODEL)/256, 256>>>(out);
}

// round 4
// speedup vs baseline: 4.8749x; 1.4565x over previous
#include <cuda_runtime.h>
#include <cuda_bf16.h>
#include <math.h>
#include <stdint.h>

// ----------------------------------------------------------------------------
// Problem constants
// ----------------------------------------------------------------------------
#define T_TOK 2048
#define D_MODEL 2048
#define N_Q 16
#define N_KV 4
#define HEAD 128
#define QH (N_Q*HEAD)      // 2048
#define KVH (N_KV*HEAD)    // 512
#define N_EXP 16
#define F_FF 1024
#define TOPK 4
#define SLOTS (T_TOK*TOPK) // 8192
#define EPS 1e-6f

// ----------------------------------------------------------------------------
// Scratch (device globals; no dynamic allocation allowed)
// ----------------------------------------------------------------------------
__device__ float g_hnorm[T_TOK*D_MODEL];
__device__ float g_q[T_TOK*QH];
__device__ float g_k[T_TOK*KVH];
__device__ float g_v[T_TOK*KVH];
__device__ float g_attn[T_TOK*QH];
__device__ float g_resid2[T_TOK*D_MODEL];
__device__ float g_h2[T_TOK*D_MODEL];
__device__ float g_topw[SLOTS];
__device__ int   g_topidx[SLOTS];
__device__ int   g_cnt[N_EXP];
__device__ int   g_off[N_EXP+1];
__device__ int   g_cursor[N_EXP];
__device__ int   g_tokperm[SLOTS];
__device__ int   g_slotrow[SLOTS];
__device__ float g_gu[(size_t)SLOTS*2048];
__device__ float g_gated[(size_t)SLOTS*F_FF];
__device__ float g_downo[(size_t)SLOTS*D_MODEL];

// ----------------------------------------------------------------------------
// tf32 helpers (baseline PTX; compute_103-safe, no 'a'-features)
// ----------------------------------------------------------------------------
__device__ __forceinline__ uint32_t f2tf(float f) {
    uint32_t u;
    asm("cvt.rna.tf32.f32 %0, %1;" : "=r"(u) : "f"(f));
    return u;
}

#define MMA_TF32(cc, aa, bb) \
    asm volatile("mma.sync.aligned.m16n8k8.row.col.f32.tf32.tf32.f32 " \
        "{%0,%1,%2,%3}, {%4,%5,%6,%7}, {%8,%9}, {%0,%1,%2,%3};" \
        : "+f"(cc[0]), "+f"(cc[1]), "+f"(cc[2]), "+f"(cc[3]) \
        : "r"(aa[0]), "r"(aa[1]), "r"(aa[2]), "r"(aa[3]), "r"(bb[0]), "r"(bb[1]))

// A tile smem: [row 0..127][k 0..31], float idx:
#define SWZA(r, c) ((r)*32 + (((((c)>>2) ^ ((r)&7))) << 2) + ((c)&3))
// B tile smem: [k 0..31][n 0..127], float idx:
#define SWZB(k, n) ((k)*128 + (((((n)>>2) ^ (((k)&3)<<1))) << 2) + ((n)&3))

// ----------------------------------------------------------------------------
// tf32 tensor-core GEMM machinery: block tile 128x128x32, 256 thr, 8 warps.
// ----------------------------------------------------------------------------
#define GBM 128
#define GBN 128
#define GBK 32
#define GEMM_SMEM (2*(4096+4096)*4)   // 65536

#define LOAD_G(IT) do {                                                        \
    const int k0_ = (IT)*GBK;                                                  \
    _Pragma("unroll")                                                          \
    for (int i_=0;i_<4;i_++) aReg[i_] = *(const float4*)(arp[i_] + k0_);       \
    const float* bp_ = Bsrc + (size_t)k0_*ldb + bn + bn4*4;                    \
    _Pragma("unroll")                                                          \
    for (int i_=0;i_<4;i_++)                                                   \
        bReg[i_] = *(const float4*)(bp_ + (size_t)(bk + i_*8)*ldb);            \
} while(0)

#define STAGE_S(S) do {                                                        \
    uint32_t* as_ = Ash + (S)*4096;                                            \
    uint32_t* bs_ = Bsh + (S)*4096;                                            \
    _Pragma("unroll")                                                          \
    for (int i_=0;i_<4;i_++) {                                                 \
        uint4 v_;                                                              \
        v_.x=f2tf(aReg[i_].x); v_.y=f2tf(aReg[i_].y);                          \
        v_.z=f2tf(aReg[i_].z); v_.w=f2tf(aReg[i_].w);                          \
        *(uint4*)(as_ + aoff[i_]) = v_;                                        \
    }                                                                          \
    _Pragma("unroll")                                                          \
    for (int i_=0;i_<4;i_++) {                                                 \
        int kk_ = bk + i_*8;                                                   \
        uint4 v_;                                                              \
        v_.x=f2tf(bReg[i_].x); v_.y=f2tf(bReg[i_].y);                          \
        v_.z=f2tf(bReg[i_].z); v_.w=f2tf(bReg[i_].w);                          \
        *(uint4*)(bs_ + kk_*128 + (((bn4 ^ ((kk_&3)<<1)))<<2)) = v_;           \
    }                                                                          \
} while(0)

#define COMPUTE_S(S) do {                                                      \
    const uint32_t* as_ = Ash + (S)*4096;                                      \
    const uint32_t* bs_ = Bsh + (S)*4096;                                      \
    _Pragma("unroll")                                                          \
    for (int ks_=0; ks_<4; ks_++) {                                            \
        const int k0_ = ks_*8;                                                 \
        uint32_t af[4][4], bf[4][2];                                           \
        _Pragma("unroll")                                                      \
        for (int mt_=0; mt_<4; mt_++) {                                        \
            int r_ = wm + mt_*16 + (lane>>2);                                  \
            af[mt_][0] = as_[SWZA(r_,   k0_+(lane&3))];                        \
            af[mt_][1] = as_[SWZA(r_+8, k0_+(lane&3))];                        \
            af[mt_][2] = as_[SWZA(r_,   k0_+4+(lane&3))];                      \
            af[mt_][3] = as_[SWZA(r_+8, k0_+4+(lane&3))];                      \
        }                                                                      \
        _Pragma("unroll")                                                      \
        for (int nt_=0; nt_<4; nt_++) {                                        \
            int n_ = wn + nt_*8 + (lane>>2);                                   \
            bf[nt_][0] = bs_[SWZB(k0_+(lane&3),   n_)];                        \
            bf[nt_][1] = bs_[SWZB(k0_+4+(lane&3), n_)];                        \
        }                                                                      \
        _Pragma("unroll")                                                      \
        for (int mt_=0; mt_<4; mt_++)                                          \
            _Pragma("unroll")                                                  \
            for (int nt_=0; nt_<4; nt_++)                                      \
                MMA_TF32(c[mt_][nt_], af[mt_], bf[nt_]);                       \
    }                                                                          \
} while(0)

// Generic GEMM. MODE 0: plain.  MODE 1: MoE gate_up.  MODE 2: MoE down.
template<int MODE>
__global__ __launch_bounds__(256)
void mma_gemm(const float* __restrict__ A, const float* __restrict__ B, int ldb,
              const float* __restrict__ Cadd, float* __restrict__ C, int ldc,
              int K)
{
    extern __shared__ uint32_t smu[];
    uint32_t* Ash = smu;            // [2][4096]
    uint32_t* Bsh = smu + 8192;     // [2][4096]

    const int tid  = threadIdx.x;
    const int lane = tid & 31;
    const int w    = tid >> 5;
    const int wm   = (w & 1) * 64;
    const int wn   = (w >> 1) * 32;
    const int bn   = blockIdx.x * GBN;
    const int m0   = blockIdx.y * GBM;

    int cnt_rows = GBM;
    int base = 0;
    size_t cBase;
    const float* Bsrc = B;
    if (MODE == 0) {
        cBase = (size_t)m0 * ldc;
    } else {
        const int e = blockIdx.z;
        const int cnt = g_cnt[e];
        if (m0 >= cnt) return;
        base = g_off[e];
        cnt_rows = min(GBM, cnt - m0);
        Bsrc = B + (size_t)e * (size_t)K * (size_t)ldb;
        cBase = (size_t)(base + m0) * ldc;
    }

    const int ac4 = tid & 7;
    const float* arp[4];
    int aoff[4];
    #pragma unroll
    for (int i = 0; i < 4; i++) {
        int row = (tid >> 3) + i * 32;
        int rl = min(row, cnt_rows - 1);
        size_t gr;
        if (MODE == 0)      gr = (size_t)(m0 + row);
        else if (MODE == 1) gr = (size_t)g_tokperm[base + m0 + rl];
        else                gr = (size_t)(base + m0 + rl);
        arp[i] = A + gr * (size_t)K + ac4 * 4;
        aoff[i] = row * 32 + ((ac4 ^ (row & 7)) << 2);
    }
    const int bk  = tid >> 5;
    const int bn4 = tid & 31;

    float4 aReg[4], bReg[4];
    float c[4][4][4] = {};

    const int nIter = K / GBK;
    LOAD_G(0);
    STAGE_S(0);
    __syncthreads();
    for (int it = 0; it < nIter; it++) {
        const int cur = it & 1;
        if (it + 1 < nIter) LOAD_G(it + 1);
        COMPUTE_S(cur);
        __syncthreads();
        if (it + 1 < nIter) {
            STAGE_S(cur ^ 1);
            __syncthreads();
        }
    }

    #pragma unroll
    for (int mt = 0; mt < 4; mt++) {
        #pragma unroll
        for (int h = 0; h < 2; h++) {
            int r = wm + mt * 16 + (lane >> 2) + h * 8;
            if (r < cnt_rows) {
                float* dst = C + cBase + (size_t)r * ldc + bn;
                const float* ad = Cadd ? (Cadd + cBase + (size_t)r * ldc + bn)
                                       : (const float*)0;
                #pragma unroll
                for (int nt = 0; nt < 4; nt++) {
                    int col = wn + nt * 8 + ((lane & 3) << 1);
                    float v0 = c[mt][nt][h * 2 + 0];
                    float v1 = c[mt][nt][h * 2 + 1];
                    if (ad) { v0 += ad[col]; v1 += ad[col + 1]; }
                    dst[col]     = v0;
                    dst[col + 1] = v1;
                }
            }
        }
    }
}

// ----------------------------------------------------------------------------
// Fused QKV GEMM: one launch covering q (2048 cols) + k (512) + v (512).
// blockIdx.x in [0,24): col-block selects which weight/output.
// ----------------------------------------------------------------------------
__global__ __launch_bounds__(256)
void mma_gemm_qkv(const float* __restrict__ A,
                  const float* __restrict__ Bq, const float* __restrict__ Bk2,
                  const float* __restrict__ Bv,
                  float* __restrict__ Cq, float* __restrict__ Ck,
                  float* __restrict__ Cv)
{
    extern __shared__ uint32_t smu[];
    uint32_t* Ash = smu;
    uint32_t* Bsh = smu + 8192;

    const int tid  = threadIdx.x;
    const int lane = tid & 31;
    const int w    = tid >> 5;
    const int wm   = (w & 1) * 64;
    const int wn   = (w >> 1) * 32;
    const int m0   = blockIdx.y * GBM;
    const int bnG  = blockIdx.x * GBN;

    const float* Bsrc;
    float* C;
    int ldb, bn;
    if (bnG < 2048)      { Bsrc = Bq;  C = Cq; ldb = 2048; bn = bnG; }
    else if (bnG < 2560) { Bsrc = Bk2; C = Ck; ldb = 512;  bn = bnG - 2048; }
    else                 { Bsrc = Bv;  C = Cv; ldb = 512;  bn = bnG - 2560; }
    const int K = 2048;

    const int ac4 = tid & 7;
    const float* arp[4];
    int aoff[4];
    #pragma unroll
    for (int i = 0; i < 4; i++) {
        int row = (tid >> 3) + i * 32;
        arp[i] = A + (size_t)(m0 + row) * K + ac4 * 4;
        aoff[i] = row * 32 + ((ac4 ^ (row & 7)) << 2);
    }
    const int bk  = tid >> 5;
    const int bn4 = tid & 31;

    float4 aReg[4], bReg[4];
    float c[4][4][4] = {};

    const int nIter = K / GBK;
    LOAD_G(0);
    STAGE_S(0);
    __syncthreads();
    for (int it = 0; it < nIter; it++) {
        const int cur = it & 1;
        if (it + 1 < nIter) LOAD_G(it + 1);
        COMPUTE_S(cur);
        __syncthreads();
        if (it + 1 < nIter) {
            STAGE_S(cur ^ 1);
            __syncthreads();
        }
    }

    #pragma unroll
    for (int mt = 0; mt < 4; mt++) {
        #pragma unroll
        for (int h = 0; h < 2; h++) {
            int r = wm + mt * 16 + (lane >> 2) + h * 8;
            float* dst = C + (size_t)(m0 + r) * ldb + bn;
            #pragma unroll
            for (int nt = 0; nt < 4; nt++) {
                int col = wn + nt * 8 + ((lane & 3) << 1);
                dst[col]     = c[mt][nt][h * 2 + 0];
                dst[col + 1] = c[mt][nt][h * 2 + 1];
            }
        }
    }
}

// ----------------------------------------------------------------------------
// tf32 mma flash attention. Block = (q-tile 128, head). 256 thr, 8 warps.
// Warp w owns rows w*16..w*16+15 entirely: softmax needs only 2-lane shfls.
// smem: Qs[128][132] tf32, Ks[64][132] tf32, Vt[128][68] tf32 (V transposed),
//       Ps[128][68] tf32.  171008 B dynamic.
// ----------------------------------------------------------------------------
#define ALD 132
#define PLD 68
#define ATTN_SMEM ((128*ALD + 64*ALD + 128*PLD + 128*PLD)*4)

__global__ __launch_bounds__(256) void attn_mma(
    const float* __restrict__ Q, const float* __restrict__ Kg,
    const float* __restrict__ Vg, float* __restrict__ O)
{
    extern __shared__ uint32_t smw[];
    uint32_t* Qs = smw;                       // 128*132
    uint32_t* Ks = smw + 128*ALD;             // 64*132
    uint32_t* Vt = Ks + 64*ALD;               // 128*68 (d-major)
    uint32_t* Ps = Vt + 128*PLD;              // 128*68

    const int h = blockIdx.y, kvh = h >> 2;
    const int qb = blockIdx.x, q0 = qb * 128;
    const int tid = threadIdx.x, lane = tid & 31, w = tid >> 5;
    const int wr0 = w * 16;
    const int rA = lane >> 2;      // 0..7
    const int kq = lane & 3;       // 0..3
    const float scale = 0.08838834764831845f; // 128^-0.5

    // Load Q tile (scale folded in, tf32)
    {
        const int c4 = tid & 31, r0 = tid >> 5;
        #pragma unroll
        for (int i = 0; i < 16; i++) {
            int r = r0 + i * 8;
            float4 v = *(const float4*)(Q + (size_t)(q0 + r) * QH + h * HEAD + c4 * 4);
            uint32_t* dst = Qs + r * ALD + c4 * 4;
            dst[0] = f2tf(v.x * scale); dst[1] = f2tf(v.y * scale);
            dst[2] = f2tf(v.z * scale); dst[3] = f2tf(v.w * scale);
        }
    }

    float mA = -1e30f, mB = -1e30f, lA = 0.f, lB = 0.f;
    float of[16][4];
    #pragma unroll
    for (int i = 0; i < 16; i++)
        { of[i][0] = 0.f; of[i][1] = 0.f; of[i][2] = 0.f; of[i][3] = 0.f; }

    const int nkb = 2 * qb + 2;
    for (int kb = 0; kb < nkb; kb++) {
        const int k0 = kb * 64;
        __syncthreads();
        // Load K tile [64][128] tf32
        {
            const int c4 = tid & 31, r0 = tid >> 5;
            #pragma unroll
            for (int i = 0; i < 8; i++) {
                int r = r0 + i * 8;
                float4 v = *(const float4*)(Kg + (size_t)(k0 + r) * KVH + kvh * HEAD + c4 * 4);
                uint32_t* dst = Ks + r * ALD + c4 * 4;
                dst[0] = f2tf(v.x); dst[1] = f2tf(v.y);
                dst[2] = f2tf(v.z); dst[3] = f2tf(v.w);
            }
            // Load V transposed: Vt[d][j]
            const int j = tid >> 2, d4 = tid & 3;
            #pragma unroll
            for (int i = 0; i < 8; i++) {
                int dd = (d4 + i * 4) * 4;
                float4 v = *(const float4*)(Vg + (size_t)(k0 + j) * KVH + kvh * HEAD + dd);
                Vt[(dd + 0) * PLD + j] = f2tf(v.x);
                Vt[(dd + 1) * PLD + j] = f2tf(v.y);
                Vt[(dd + 2) * PLD + j] = f2tf(v.z);
                Vt[(dd + 3) * PLD + j] = f2tf(v.w);
            }
        }
        __syncthreads();
        if (q0 + wr0 + 15 < k0) continue;   // warp fully below-diagonal-masked

        // S = Q K^T  (warp: 16 rows x 64 cols)
        float sf[8][4];
        #pragma unroll
        for (int nt = 0; nt < 8; nt++)
            { sf[nt][0]=0.f; sf[nt][1]=0.f; sf[nt][2]=0.f; sf[nt][3]=0.f; }
        #pragma unroll
        for (int ks = 0; ks < 16; ks++) {
            uint32_t aa[4];
            aa[0] = Qs[(wr0 + rA)     * ALD + ks * 8 + kq];
            aa[1] = Qs[(wr0 + rA + 8) * ALD + ks * 8 + kq];
            aa[2] = Qs[(wr0 + rA)     * ALD + ks * 8 + 4 + kq];
            aa[3] = Qs[(wr0 + rA + 8) * ALD + ks * 8 + 4 + kq];
            #pragma unroll
            for (int nt = 0; nt < 8; nt++) {
                uint32_t bb[2];
                bb[0] = Ks[(nt * 8 + rA) * ALD + ks * 8 + kq];
                bb[1] = Ks[(nt * 8 + rA) * ALD + ks * 8 + 4 + kq];
                MMA_TF32(sf[nt], aa, bb);
            }
        }

        // mask + online softmax
        const int rowA = q0 + wr0 + rA;
        const int rowB = rowA + 8;
        if (kb >= 2 * qb) {
            #pragma unroll
            for (int nt = 0; nt < 8; nt++) {
                #pragma unroll
                for (int u = 0; u < 2; u++) {
                    int col = k0 + nt * 8 + kq * 2 + u;
                    if (col > rowA) sf[nt][u]     = -1e30f;
                    if (col > rowB) sf[nt][2 + u] = -1e30f;
                }
            }
        }
        float mxA = -1e30f, mxB = -1e30f;
        #pragma unroll
        for (int nt = 0; nt < 8; nt++) {
            mxA = fmaxf(mxA, fmaxf(sf[nt][0], sf[nt][1]));
            mxB = fmaxf(mxB, fmaxf(sf[nt][2], sf[nt][3]));
        }
        mxA = fmaxf(mxA, __shfl_xor_sync(0xffffffffu, mxA, 1));
        mxA = fmaxf(mxA, __shfl_xor_sync(0xffffffffu, mxA, 2));
        mxB = fmaxf(mxB, __shfl_xor_sync(0xffffffffu, mxB, 1));
        mxB = fmaxf(mxB, __shfl_xor_sync(0xffffffffu, mxB, 2));
        float mnA = fmaxf(mA, mxA), mnB = fmaxf(mB, mxB);
        float cA = __expf(mA - mnA), cB = __expf(mB - mnB);
        mA = mnA; mB = mnB;
        float rsA = 0.f, rsB = 0.f;
        #pragma unroll
        for (int nt = 0; nt < 8; nt++) {
            float p0 = __expf(sf[nt][0] - mnA), p1 = __expf(sf[nt][1] - mnA);
            float p2 = __expf(sf[nt][2] - mnB), p3 = __expf(sf[nt][3] - mnB);
            rsA += p0 + p1; rsB += p2 + p3;
            uint2 pa; pa.x = f2tf(p0); pa.y = f2tf(p1);
            *(uint2*)&Ps[(wr0 + rA)     * PLD + nt * 8 + kq * 2] = pa;
            uint2 pb; pb.x = f2tf(p2); pb.y = f2tf(p3);
            *(uint2*)&Ps[(wr0 + rA + 8) * PLD + nt * 8 + kq * 2] = pb;
        }
        rsA += __shfl_xor_sync(0xffffffffu, rsA, 1);
        rsA += __shfl_xor_sync(0xffffffffu, rsA, 2);
        rsB += __shfl_xor_sync(0xffffffffu, rsB, 1);
        rsB += __shfl_xor_sync(0xffffffffu, rsB, 2);
        lA = lA * cA + rsA; lB = lB * cB + rsB;
        #pragma unroll
        for (int nt2 = 0; nt2 < 16; nt2++) {
            of[nt2][0] *= cA; of[nt2][1] *= cA;
            of[nt2][2] *= cB; of[nt2][3] *= cB;
        }
        __syncwarp();

        // O += P V  (A = Ps rows of this warp, B = Vt)
        #pragma unroll
        for (int ks = 0; ks < 8; ks++) {
            uint32_t aa[4];
            aa[0] = Ps[(wr0 + rA)     * PLD + ks * 8 + kq];
            aa[1] = Ps[(wr0 + rA + 8) * PLD + ks * 8 + kq];
            aa[2] = Ps[(wr0 + rA)     * PLD + ks * 8 + 4 + kq];
            aa[3] = Ps[(wr0 + rA + 8) * PLD + ks * 8 + 4 + kq];
            #pragma unroll
            for (int nt2 = 0; nt2 < 16; nt2++) {
                uint32_t bb[2];
                bb[0] = Vt[(nt2 * 8 + rA) * PLD + ks * 8 + kq];
                bb[1] = Vt[(nt2 * 8 + rA) * PLD + ks * 8 + 4 + kq];
                MMA_TF32(of[nt2], aa, bb);
            }
        }
    }

    // epilogue
    const float iA = 1.f / lA, iB = 1.f / lB;
    const int rowA = q0 + wr0 + rA, rowB = rowA + 8;
    #pragma unroll
    for (int nt2 = 0; nt2 < 16; nt2++) {
        int col = h * HEAD + nt2 * 8 + kq * 2;
        float2 va; va.x = of[nt2][0] * iA; va.y = of[nt2][1] * iA;
        *(float2*)&O[(size_t)rowA * QH + col] = va;
        float2 vb; vb.x = of[nt2][2] * iB; vb.y = of[nt2][3] * iB;
        *(float2*)&O[(size_t)rowB * QH + col] = vb;
    }
}

// ----------------------------------------------------------------------------
// RMSNorm over D=2048, one block per row
// ----------------------------------------------------------------------------
__global__ __launch_bounds__(256) void rmsnorm_kernel(
    const float* __restrict__ x, const float* __restrict__ w, float* __restrict__ out)
{
    const int t = blockIdx.x, tid = threadIdx.x;
    const float4* xr = (const float4*)(x + (size_t)t*D_MODEL);
    float4 a = xr[tid], b = xr[tid+256];
    float ss = a.x*a.x + a.y*a.y + a.z*a.z + a.w*a.w
             + b.x*b.x + b.y*b.y + b.z*b.z + b.w*b.w;
    #pragma unroll
    for (int off=16; off>0; off>>=1) ss += __shfl_xor_sync(0xffffffffu, ss, off);
    __shared__ float red[8];
    if ((tid&31)==0) red[tid>>5] = ss;
    __syncthreads();
    float tot = red[0]+red[1]+red[2]+red[3]+red[4]+red[5]+red[6]+red[7];
    float inv = rsqrtf(tot/(float)D_MODEL + EPS);
    const float4* wr = (const float4*)w;
    float4 wa = wr[tid], wb = wr[tid+256];
    float4* orow = (float4*)(out + (size_t)t*D_MODEL);
    orow[tid]     = make_float4(a.x*inv*wa.x, a.y*inv*wa.y, a.z*inv*wa.z, a.w*inv*wa.w);
    orow[tid+256] = make_float4(b.x*inv*wb.x, b.y*inv*wb.y, b.z*inv*wb.z, b.w*inv*wb.w);
}

// ----------------------------------------------------------------------------
// Per-head RMSNorm (H=128) + RoPE. One block (128 thr) per row.
// ----------------------------------------------------------------------------
__global__ __launch_bounds__(128) void qknorm_rope(
    float* __restrict__ x, const float* __restrict__ nw,
    const float* __restrict__ cosb, const float* __restrict__ sinb, int NH)
{
    const int row = blockIdx.x;
    const int t = row / NH;
    const int tid = threadIdx.x;
    float v = x[(size_t)row*HEAD + tid];
    float ss = v*v;
    #pragma unroll
    for (int off=16; off>0; off>>=1) ss += __shfl_xor_sync(0xffffffffu, ss, off);
    __shared__ float red[4];
    __shared__ float xs[HEAD];
    if ((tid&31)==0) red[tid>>5] = ss;
    __syncthreads();
    float tot = red[0]+red[1]+red[2]+red[3];
    float inv = rsqrtf(tot/(float)HEAD + EPS);
    float xn = v*inv*nw[tid];
    xs[tid] = xn;
    __syncthreads();
    float other = xs[tid^64];
    float c = cosb[(size_t)t*HEAD + tid];
    float s = sinb[(size_t)t*HEAD + tid];
    float outv = (tid < 64) ? (xn*c - other*s) : (xn*c + other*s);
    x[(size_t)row*HEAD + tid] = outv;
}

// ----------------------------------------------------------------------------
// MoE router + permutation machinery
// ----------------------------------------------------------------------------
__global__ __launch_bounds__(128) void router_kernel(
    const float* __restrict__ h2, const float* __restrict__ gw)
{
    const int t = blockIdx.x, tid = threadIdx.x;
    const int e = tid & 15, c = tid >> 4;
    const float* x = h2 + (size_t)t*D_MODEL;
    float acc = 0.f;
    for (int d = c*256; d < c*256+256; d++)
        acc += x[d]*gw[d*N_EXP + e];
    __shared__ float part[8][16];
    part[c][e] = acc;
    __syncthreads();
    if (tid == 0) {
        float lg[16];
        for (int ee=0; ee<16; ee++) {
            float s = 0.f;
            for (int cc=0; cc<8; cc++) s += part[cc][ee];
            lg[ee] = s;
        }
        float mx = lg[0];
        for (int ee=1; ee<16; ee++) mx = fmaxf(mx, lg[ee]);
        float pb[16]; float sum = 0.f;
        for (int ee=0; ee<16; ee++) { pb[ee] = expf(lg[ee]-mx); sum += pb[ee]; }
        float isum = 1.f/sum;
        for (int ee=0; ee<16; ee++) pb[ee] *= isum;
        bool used[16] = {};
        int idx4[4]; float w4[4]; float wsum = 0.f;
        for (int s4=0; s4<4; s4++) {
            int bi = -1; float bv = -1.f;
            for (int ee=0; ee<16; ee++)
                if (!used[ee] && pb[ee] > bv) { bv = pb[ee]; bi = ee; }
            used[bi] = true; idx4[s4] = bi; w4[s4] = bv; wsum += bv;
        }
        for (int s4=0; s4<4; s4++) {
            g_topidx[t*4+s4] = idx4[s4];
            g_topw[t*4+s4]   = w4[s4]/wsum;
            atomicAdd(&g_cnt[idx4[s4]], 1);
        }
    }
}

__global__ void zero_kernel() {
    if (threadIdx.x < N_EXP) g_cnt[threadIdx.x] = 0;
}
__global__ void offsets_kernel() {
    if (threadIdx.x == 0) {
        int acc = 0;
        for (int e=0; e<N_EXP; e++) { g_off[e] = acc; acc += g_cnt[e]; g_cursor[e] = 0; }
        g_off[N_EXP] = acc;
    }
}
__global__ __launch_bounds__(256) void scatter_kernel() {
    int idx = blockIdx.x*blockDim.x + threadIdx.x;
    if (idx >= SLOTS) return;
    int t = idx >> 2;
    int e = g_topidx[idx];
    int p = atomicAdd(&g_cursor[e], 1);
    int r = g_off[e] + p;
    g_tokperm[r] = t;
    g_slotrow[idx] = r;
}

// silu over float4: SLOTS rows, 256 float4 per row output
__global__ __launch_bounds__(256) void silu_kernel() {
    int idx = blockIdx.x*blockDim.x + threadIdx.x;
    if (idx >= SLOTS*256) return;
    int r = idx >> 8, f4 = idx & 255;
    const float4* gu = (const float4*)(g_gu + (size_t)r*2048);
    float4 g4 = gu[f4];
    float4 u4 = gu[256 + f4];
    float4 o;
    o.x = u4.x * (g4.x / (1.f + __expf(-g4.x)));
    o.y = u4.y * (g4.y / (1.f + __expf(-g4.y)));
    o.z = u4.z * (g4.z / (1.f + __expf(-g4.z)));
    o.w = u4.w * (g4.w / (1.f + __expf(-g4.w)));
    ((float4*)(g_gated + (size_t)r*F_FF))[f4] = o;
}

// combine over float4: out = resid2 + sum topw * downo[slotrow]
__global__ __launch_bounds__(256) void combine_kernel(float* __restrict__ out)
{
    int idx = blockIdx.x*blockDim.x + threadIdx.x;
    if (idx >= T_TOK*512) return;
    int t = idx >> 9, d4 = idx & 511;
    float4 acc = ((const float4*)(g_resid2 + (size_t)t*2048))[d4];
    #pragma unroll
    for (int s=0; s<4; s++) {
        int row = g_slotrow[t*4+s];
        float wgt = g_topw[t*4+s];
        float4 v = ((const float4*)(g_downo + (size_t)row*2048))[d4];
        acc.x += wgt*v.x; acc.y += wgt*v.y; acc.z += wgt*v.z; acc.w += wgt*v.w;
    }
    ((float4*)out)[idx] = acc;
}

// ----------------------------------------------------------------------------
// Launcher
// ----------------------------------------------------------------------------
extern "C" void kernel_launch(void* const* d_in, const int* in_sizes, int n_in,
                              void* d_out, int out_size)
{
    const float* hidden = (const float*)d_in[0];
    const float* cosb   = (const float*)d_in[1];
    const float* sinb   = (const float*)d_in[2];
    // d_in[3] attention_mask: exactly causal; applied analytically in-kernel
    const float* iln    = (const float*)d_in[4];
    const float* pln    = (const float*)d_in[5];
    const float* qw     = (const float*)d_in[6];
    const float* kw     = (const float*)d_in[7];
    const float* vw     = (const float*)d_in[8];
    const float* ow     = (const float*)d_in[9];
    const float* qnw    = (const float*)d_in[10];
    const float* knw    = (const float*)d_in[11];
    const float* gw     = (const float*)d_in[12];
    const float* guw    = (const float*)d_in[13];
    const float* dww    = (const float*)d_in[14];
    float* out = (float*)d_out;

    cudaFuncSetAttribute(attn_mma,     cudaFuncAttributeMaxDynamicSharedMemorySize, ATTN_SMEM);
    cudaFuncSetAttribute(mma_gemm_qkv, cudaFuncAttributeMaxDynamicSharedMemorySize, GEMM_SMEM);
    cudaFuncSetAttribute(mma_gemm<0>,  cudaFuncAttributeMaxDynamicSharedMemorySize, GEMM_SMEM);
    cudaFuncSetAttribute(mma_gemm<1>,  cudaFuncAttributeMaxDynamicSharedMemorySize, GEMM_SMEM);
    cudaFuncSetAttribute(mma_gemm<2>,  cudaFuncAttributeMaxDynamicSharedMemorySize, GEMM_SMEM);

    void* p;
    cudaGetSymbolAddress(&p, g_hnorm);  float* hnorm  = (float*)p;
    cudaGetSymbolAddress(&p, g_q);      float* qbuf   = (float*)p;
    cudaGetSymbolAddress(&p, g_k);      float* kbuf   = (float*)p;
    cudaGetSymbolAddress(&p, g_v);      float* vbuf   = (float*)p;
    cudaGetSymbolAddress(&p, g_attn);   float* abuf   = (float*)p;
    cudaGetSymbolAddress(&p, g_resid2); float* resid2 = (float*)p;
    cudaGetSymbolAddress(&p, g_h2);     float* h2buf  = (float*)p;
    cudaGetSymbolAddress(&p, g_gu);     float* gubuf  = (float*)p;
    cudaGetSymbolAddress(&p, g_gated);  float* gtbuf  = (float*)p;
    cudaGetSymbolAddress(&p, g_downo);  float* dobuf  = (float*)p;

    // 1) input RMSNorm
    rmsnorm_kernel<<<T_TOK, 256>>>(hidden, iln, hnorm);
    // 2) fused QKV projection (tf32 mma)
    mma_gemm_qkv<<<dim3(24, T_TOK/128), 256, GEMM_SMEM>>>(hnorm, qw, kw, vw, qbuf, kbuf, vbuf);
    // 3) per-head norm + RoPE
    qknorm_rope<<<T_TOK*N_Q,  128>>>(qbuf, qnw, cosb, sinb, N_Q);
    qknorm_rope<<<T_TOK*N_KV, 128>>>(kbuf, knw, cosb, sinb, N_KV);
    // 4) causal GQA attention (tf32 mma)
    attn_mma<<<dim3(T_TOK/128, N_Q), 256, ATTN_SMEM>>>(qbuf, kbuf, vbuf, abuf);
    // 5) O projection + residual add
    mma_gemm<0><<<dim3(D_MODEL/128, T_TOK/128), 256, GEMM_SMEM>>>(abuf, ow, D_MODEL, hidden, resid2, D_MODEL, QH);
    // 6) post RMSNorm
    rmsnorm_kernel<<<T_TOK, 256>>>(resid2, pln, h2buf);
    // 7) MoE routing + expert permutation
    zero_kernel<<<1, 32>>>();
    router_kernel<<<T_TOK, 128>>>(h2buf, gw);
    offsets_kernel<<<1, 1>>>();
    scatter_kernel<<<SLOTS/256, 256>>>();
    // 8) sparse expert GEMMs (tf32 mma)
    mma_gemm<1><<<dim3(2048/128, T_TOK/128, N_EXP), 256, GEMM_SMEM>>>(h2buf, guw, 2048, nullptr, gubuf, 2048, 2048);
    silu_kernel<<<(SLOTS*256)/256, 256>>>();
    mma_gemm<2><<<dim3(D_MODEL/128, T_TOK/128, N_EXP), 256, GEMM_SMEM>>>(gtbuf, dww, 2048, nullptr, dobuf, 2048, 1024);
    // 9) weighted combine + residual
    combine_kernel<<<(T_TOK*512)/256, 256>>>(out);
}

// round 5
// speedup vs baseline: 7.0682x; 1.4499x over previous
#include <cuda_runtime.h>
#include <cuda_bf16.h>
#include <math.h>
#include <stdint.h>

// ----------------------------------------------------------------------------
// Problem constants
// ----------------------------------------------------------------------------
#define T_TOK 2048
#define D_MODEL 2048
#define N_Q 16
#define N_KV 4
#define HEAD 128
#define QH (N_Q*HEAD)      // 2048
#define KVH (N_KV*HEAD)    // 512
#define N_EXP 16
#define F_FF 1024
#define TOPK 4
#define SLOTS (T_TOK*TOPK) // 8192
#define EPS 1e-6f

// ----------------------------------------------------------------------------
// Scratch (device globals; no dynamic allocation allowed)
// ----------------------------------------------------------------------------
__device__ float g_hnorm[T_TOK*D_MODEL];
__device__ float g_q[T_TOK*QH];
__device__ float g_k[T_TOK*KVH];
__device__ float g_v[T_TOK*KVH];
__device__ float g_attn[T_TOK*QH];
__device__ float g_resid2[T_TOK*D_MODEL];
__device__ float g_h2[T_TOK*D_MODEL];
__device__ float g_topw[SLOTS];
__device__ int   g_topidx[SLOTS];
__device__ int   g_cnt[N_EXP];
__device__ int   g_off[N_EXP+1];
__device__ int   g_cursor[N_EXP];
__device__ int   g_tokperm[SLOTS];
__device__ int   g_slotrow[SLOTS];
__device__ float g_gu[(size_t)SLOTS*2048];
__device__ float g_gated[(size_t)SLOTS*F_FF];
__device__ float g_downo[(size_t)SLOTS*D_MODEL];

// ----------------------------------------------------------------------------
// helpers (baseline PTX; compute_103-safe, no 'a'-features)
// ----------------------------------------------------------------------------
__device__ __forceinline__ uint32_t f2tf(float f) {
    uint32_t u;
    asm("cvt.rna.tf32.f32 %0, %1;" : "=r"(u) : "f"(f));
    return u;
}
__device__ __forceinline__ uint32_t smem_u32(const void* p) {
    uint32_t a;
    asm("{ .reg .u64 t; cvta.to.shared.u64 t, %1; cvt.u32.u64 %0, t; }"
        : "=r"(a) : "l"(p));
    return a;
}
__device__ __forceinline__ void cp16(uint32_t dst, const void* src) {
    asm volatile("cp.async.cg.shared.global [%0], [%1], 16;" :: "r"(dst), "l"(src));
}

#define MMA_TF32(cc, aa, bb) \
    asm volatile("mma.sync.aligned.m16n8k8.row.col.f32.tf32.tf32.f32 " \
        "{%0,%1,%2,%3}, {%4,%5,%6,%7}, {%8,%9}, {%0,%1,%2,%3};" \
        : "+f"(cc[0]), "+f"(cc[1]), "+f"(cc[2]), "+f"(cc[3]) \
        : "r"(aa[0]), "r"(aa[1]), "r"(aa[2]), "r"(aa[3]), "r"(bb[0]), "r"(bb[1]))

// A tile smem: [row 0..127][k 0..31], float idx:
#define SWZA(r, c) ((r)*32 + (((((c)>>2) ^ ((r)&7))) << 2) + ((c)&3))
// B tile smem: [k 0..31][n 0..127], float idx:
#define SWZB(k, n) ((k)*128 + (((((n)>>2) ^ (((k)&3)<<1))) << 2) + ((n)&3))

// ----------------------------------------------------------------------------
// tf32 tensor-core GEMM: block tile 128x128x32, 256 thr, 8 warps.
// 3-stage cp.async pipeline (raw fp32 bits fed to tf32 mma: HW truncation).
// Stage = A 16KB + B 16KB = 32KB;  3 stages = 96KB -> 2 CTAs/SM.
// ----------------------------------------------------------------------------
#define GBM 128
#define GBN 128
#define GBK 32
#define NSTG 3
#define GEMM_SMEM (NSTG*32768)

#define ISSUE_S(S, IT) do {                                                    \
    const int k0_ = (IT)*GBK;                                                  \
    uint32_t ab_ = smemU + (uint32_t)(S)*32768u;                               \
    uint32_t bb_ = ab_ + 16384u;                                               \
    _Pragma("unroll")                                                          \
    for (int i_=0;i_<4;i_++) cp16(ab_ + aoffB[i_], arp[i_] + k0_);             \
    _Pragma("unroll")                                                          \
    for (int i_=0;i_<4;i_++) cp16(bb_ + boffB[i_], brp[i_] + (size_t)k0_*ldb); \
    asm volatile("cp.async.commit_group;" ::: "memory");                       \
} while(0)

#define COMPUTE_S(S) do {                                                      \
    const uint32_t* as_ = smu + (S)*8192;                                      \
    const uint32_t* bs_ = as_ + 4096;                                          \
    _Pragma("unroll")                                                          \
    for (int ks_=0; ks_<4; ks_++) {                                            \
        const int k0_ = ks_*8;                                                 \
        uint32_t af[4][4], bf[4][2];                                           \
        _Pragma("unroll")                                                      \
        for (int mt_=0; mt_<4; mt_++) {                                        \
            int r_ = wm + mt_*16 + (lane>>2);                                  \
            af[mt_][0] = as_[SWZA(r_,   k0_+(lane&3))];                        \
            af[mt_][1] = as_[SWZA(r_+8, k0_+(lane&3))];                        \
            af[mt_][2] = as_[SWZA(r_,   k0_+4+(lane&3))];                      \
            af[mt_][3] = as_[SWZA(r_+8, k0_+4+(lane&3))];                      \
        }                                                                      \
        _Pragma("unroll")                                                      \
        for (int nt_=0; nt_<4; nt_++) {                                        \
            int n_ = wn + nt_*8 + (lane>>2);                                   \
            bf[nt_][0] = bs_[SWZB(k0_+(lane&3),   n_)];                        \
            bf[nt_][1] = bs_[SWZB(k0_+4+(lane&3), n_)];                        \
        }                                                                      \
        _Pragma("unroll")                                                      \
        for (int mt_=0; mt_<4; mt_++)                                          \
            _Pragma("unroll")                                                  \
            for (int nt_=0; nt_<4; nt_++)                                      \
                MMA_TF32(c[mt_][nt_], af[mt_], bf[nt_]);                       \
    }                                                                          \
} while(0)

#define GEMM_PIPELINE()                                                        \
    const int nIter = K / GBK;                                                 \
    ISSUE_S(0, 0);                                                             \
    ISSUE_S(1, 1);                                                             \
    for (int it = 0; it < nIter; it++) {                                       \
        const int s = it % NSTG;                                               \
        asm volatile("cp.async.wait_group 1;" ::: "memory");                   \
        __syncthreads();                                                       \
        if (it + 2 < nIter) { ISSUE_S((it+2) % NSTG, it+2); }                  \
        else { asm volatile("cp.async.commit_group;" ::: "memory"); }          \
        COMPUTE_S(s);                                                          \
    }

// Generic GEMM. MODE 0: plain.  MODE 1: MoE gate_up.  MODE 2: MoE down.
template<int MODE>
__global__ __launch_bounds__(256, 2)
void mma_gemm(const float* __restrict__ A, const float* __restrict__ B, int ldb,
              const float* __restrict__ Cadd, float* __restrict__ C, int ldc,
              int K)
{
    extern __shared__ uint32_t smu[];
    const uint32_t smemU = smem_u32(smu);

    const int tid  = threadIdx.x;
    const int lane = tid & 31;
    const int w    = tid >> 5;
    const int wm   = (w & 1) * 64;
    const int wn   = (w >> 1) * 32;
    const int bn   = blockIdx.x * GBN;
    const int m0   = blockIdx.y * GBM;

    int cnt_rows = GBM;
    int base = 0;
    size_t cBase;
    const float* Bsrc = B;
    if (MODE == 0) {
        cBase = (size_t)m0 * ldc;
    } else {
        const int e = blockIdx.z;
        const int cnt = g_cnt[e];
        if (m0 >= cnt) return;
        base = g_off[e];
        cnt_rows = min(GBM, cnt - m0);
        Bsrc = B + (size_t)e * (size_t)K * (size_t)ldb;
        cBase = (size_t)(base + m0) * ldc;
    }

    // A staging: thread covers rows (tid>>3)+i*32, float4-chunk col tid&7
    const int ac4 = tid & 7;
    const float* arp[4];
    uint32_t aoffB[4];
    #pragma unroll
    for (int i = 0; i < 4; i++) {
        int row = (tid >> 3) + i * 32;
        int rl = min(row, cnt_rows - 1);
        size_t gr;
        if (MODE == 0)      gr = (size_t)(m0 + row);
        else if (MODE == 1) gr = (size_t)g_tokperm[base + m0 + rl];
        else                gr = (size_t)(base + m0 + rl);
        arp[i] = A + gr * (size_t)K + ac4 * 4;
        aoffB[i] = 4u * (uint32_t)(row * 32 + ((ac4 ^ (row & 7)) << 2));
    }
    // B staging: thread covers k rows (tid>>5)+i*8, float4-chunk col tid&31
    const int bk  = tid >> 5;
    const int bn4 = tid & 31;
    const float* brp[4];
    uint32_t boffB[4];
    #pragma unroll
    for (int i = 0; i < 4; i++) {
        int kk = bk + i * 8;
        brp[i] = Bsrc + (size_t)kk * ldb + bn + bn4 * 4;
        boffB[i] = 4u * (uint32_t)(kk * 128 + ((bn4 ^ ((kk & 3) << 1)) << 2));
    }

    float c[4][4][4] = {};
    GEMM_PIPELINE();

    #pragma unroll
    for (int mt = 0; mt < 4; mt++) {
        #pragma unroll
        for (int h = 0; h < 2; h++) {
            int r = wm + mt * 16 + (lane >> 2) + h * 8;
            if (r < cnt_rows) {
                float* dst = C + cBase + (size_t)r * ldc + bn;
                const float* ad = Cadd ? (Cadd + cBase + (size_t)r * ldc + bn)
                                       : (const float*)0;
                #pragma unroll
                for (int nt = 0; nt < 4; nt++) {
                    int col = wn + nt * 8 + ((lane & 3) << 1);
                    float v0 = c[mt][nt][h * 2 + 0];
                    float v1 = c[mt][nt][h * 2 + 1];
                    if (ad) { v0 += ad[col]; v1 += ad[col + 1]; }
                    dst[col]     = v0;
                    dst[col + 1] = v1;
                }
            }
        }
    }
}

// ----------------------------------------------------------------------------
// Fused QKV GEMM: q (2048 cols) + k (512) + v (512) in one launch.
// ----------------------------------------------------------------------------
__global__ __launch_bounds__(256, 2)
void mma_gemm_qkv(const float* __restrict__ A,
                  const float* __restrict__ Bq, const float* __restrict__ Bk2,
                  const float* __restrict__ Bv,
                  float* __restrict__ Cq, float* __restrict__ Ck,
                  float* __restrict__ Cv)
{
    extern __shared__ uint32_t smu[];
    const uint32_t smemU = smem_u32(smu);

    const int tid  = threadIdx.x;
    const int lane = tid & 31;
    const int w    = tid >> 5;
    const int wm   = (w & 1) * 64;
    const int wn   = (w >> 1) * 32;
    const int m0   = blockIdx.y * GBM;
    const int bnG  = blockIdx.x * GBN;

    const float* Bsrc;
    float* C;
    int ldb, bn;
    if (bnG < 2048)      { Bsrc = Bq;  C = Cq; ldb = 2048; bn = bnG; }
    else if (bnG < 2560) { Bsrc = Bk2; C = Ck; ldb = 512;  bn = bnG - 2048; }
    else                 { Bsrc = Bv;  C = Cv; ldb = 512;  bn = bnG - 2560; }
    const int K = 2048;

    const int ac4 = tid & 7;
    const float* arp[4];
    uint32_t aoffB[4];
    #pragma unroll
    for (int i = 0; i < 4; i++) {
        int row = (tid >> 3) + i * 32;
        arp[i] = A + (size_t)(m0 + row) * K + ac4 * 4;
        aoffB[i] = 4u * (uint32_t)(row * 32 + ((ac4 ^ (row & 7)) << 2));
    }
    const int bk  = tid >> 5;
    const int bn4 = tid & 31;
    const float* brp[4];
    uint32_t boffB[4];
    #pragma unroll
    for (int i = 0; i < 4; i++) {
        int kk = bk + i * 8;
        brp[i] = Bsrc + (size_t)kk * ldb + bn + bn4 * 4;
        boffB[i] = 4u * (uint32_t)(kk * 128 + ((bn4 ^ ((kk & 3) << 1)) << 2));
    }

    float c[4][4][4] = {};
    GEMM_PIPELINE();

    #pragma unroll
    for (int mt = 0; mt < 4; mt++) {
        #pragma unroll
        for (int h = 0; h < 2; h++) {
            int r = wm + mt * 16 + (lane >> 2) + h * 8;
            float* dst = C + (size_t)(m0 + r) * ldb + bn;
            #pragma unroll
            for (int nt = 0; nt < 4; nt++) {
                int col = wn + nt * 8 + ((lane & 3) << 1);
                dst[col]     = c[mt][nt][h * 2 + 0];
                dst[col + 1] = c[mt][nt][h * 2 + 1];
            }
        }
    }
}

// ----------------------------------------------------------------------------
// tf32 mma flash attention (unchanged from R4). Block = (q-tile 128, head).
// ----------------------------------------------------------------------------
#define ALD 132
#define PLD 68
#define ATTN_SMEM ((128*ALD + 64*ALD + 128*PLD + 128*PLD)*4)

__global__ __launch_bounds__(256) void attn_mma(
    const float* __restrict__ Q, const float* __restrict__ Kg,
    const float* __restrict__ Vg, float* __restrict__ O)
{
    extern __shared__ uint32_t smw[];
    uint32_t* Qs = smw;                       // 128*132
    uint32_t* Ks = smw + 128*ALD;             // 64*132
    uint32_t* Vt = Ks + 64*ALD;               // 128*68 (d-major)
    uint32_t* Ps = Vt + 128*PLD;              // 128*68

    const int h = blockIdx.y, kvh = h >> 2;
    const int qb = blockIdx.x, q0 = qb * 128;
    const int tid = threadIdx.x, lane = tid & 31, w = tid >> 5;
    const int wr0 = w * 16;
    const int rA = lane >> 2;      // 0..7
    const int kq = lane & 3;       // 0..3
    const float scale = 0.08838834764831845f; // 128^-0.5

    {
        const int c4 = tid & 31, r0 = tid >> 5;
        #pragma unroll
        for (int i = 0; i < 16; i++) {
            int r = r0 + i * 8;
            float4 v = *(const float4*)(Q + (size_t)(q0 + r) * QH + h * HEAD + c4 * 4);
            uint32_t* dst = Qs + r * ALD + c4 * 4;
            dst[0] = f2tf(v.x * scale); dst[1] = f2tf(v.y * scale);
            dst[2] = f2tf(v.z * scale); dst[3] = f2tf(v.w * scale);
        }
    }

    float mA = -1e30f, mB = -1e30f, lA = 0.f, lB = 0.f;
    float of[16][4];
    #pragma unroll
    for (int i = 0; i < 16; i++)
        { of[i][0] = 0.f; of[i][1] = 0.f; of[i][2] = 0.f; of[i][3] = 0.f; }

    const int nkb = 2 * qb + 2;
    for (int kb = 0; kb < nkb; kb++) {
        const int k0 = kb * 64;
        __syncthreads();
        {
            const int c4 = tid & 31, r0 = tid >> 5;
            #pragma unroll
            for (int i = 0; i < 8; i++) {
                int r = r0 + i * 8;
                float4 v = *(const float4*)(Kg + (size_t)(k0 + r) * KVH + kvh * HEAD + c4 * 4);
                uint32_t* dst = Ks + r * ALD + c4 * 4;
                dst[0] = f2tf(v.x); dst[1] = f2tf(v.y);
                dst[2] = f2tf(v.z); dst[3] = f2tf(v.w);
            }
            const int j = tid >> 2, d4 = tid & 3;
            #pragma unroll
            for (int i = 0; i < 8; i++) {
                int dd = (d4 + i * 4) * 4;
                float4 v = *(const float4*)(Vg + (size_t)(k0 + j) * KVH + kvh * HEAD + dd);
                Vt[(dd + 0) * PLD + j] = f2tf(v.x);
                Vt[(dd + 1) * PLD + j] = f2tf(v.y);
                Vt[(dd + 2) * PLD + j] = f2tf(v.z);
                Vt[(dd + 3) * PLD + j] = f2tf(v.w);
            }
        }
        __syncthreads();
        if (q0 + wr0 + 15 < k0) continue;

        float sf[8][4];
        #pragma unroll
        for (int nt = 0; nt < 8; nt++)
            { sf[nt][0]=0.f; sf[nt][1]=0.f; sf[nt][2]=0.f; sf[nt][3]=0.f; }
        #pragma unroll
        for (int ks = 0; ks < 16; ks++) {
            uint32_t aa[4];
            aa[0] = Qs[(wr0 + rA)     * ALD + ks * 8 + kq];
            aa[1] = Qs[(wr0 + rA + 8) * ALD + ks * 8 + kq];
            aa[2] = Qs[(wr0 + rA)     * ALD + ks * 8 + 4 + kq];
            aa[3] = Qs[(wr0 + rA + 8) * ALD + ks * 8 + 4 + kq];
            #pragma unroll
            for (int nt = 0; nt < 8; nt++) {
                uint32_t bb[2];
                bb[0] = Ks[(nt * 8 + rA) * ALD + ks * 8 + kq];
                bb[1] = Ks[(nt * 8 + rA) * ALD + ks * 8 + 4 + kq];
                MMA_TF32(sf[nt], aa, bb);
            }
        }

        const int rowA = q0 + wr0 + rA;
        const int rowB = rowA + 8;
        if (kb >= 2 * qb) {
            #pragma unroll
            for (int nt = 0; nt < 8; nt++) {
                #pragma unroll
                for (int u = 0; u < 2; u++) {
                    int col = k0 + nt * 8 + kq * 2 + u;
                    if (col > rowA) sf[nt][u]     = -1e30f;
                    if (col > rowB) sf[nt][2 + u] = -1e30f;
                }
            }
        }
        float mxA = -1e30f, mxB = -1e30f;
        #pragma unroll
        for (int nt = 0; nt < 8; nt++) {
            mxA = fmaxf(mxA, fmaxf(sf[nt][0], sf[nt][1]));
            mxB = fmaxf(mxB, fmaxf(sf[nt][2], sf[nt][3]));
        }
        mxA = fmaxf(mxA, __shfl_xor_sync(0xffffffffu, mxA, 1));
        mxA = fmaxf(mxA, __shfl_xor_sync(0xffffffffu, mxA, 2));
        mxB = fmaxf(mxB, __shfl_xor_sync(0xffffffffu, mxB, 1));
        mxB = fmaxf(mxB, __shfl_xor_sync(0xffffffffu, mxB, 2));
        float mnA = fmaxf(mA, mxA), mnB = fmaxf(mB, mxB);
        float cA = __expf(mA - mnA), cB = __expf(mB - mnB);
        mA = mnA; mB = mnB;
        float rsA = 0.f, rsB = 0.f;
        #pragma unroll
        for (int nt = 0; nt < 8; nt++) {
            float p0 = __expf(sf[nt][0] - mnA), p1 = __expf(sf[nt][1] - mnA);
            float p2 = __expf(sf[nt][2] - mnB), p3 = __expf(sf[nt][3] - mnB);
            rsA += p0 + p1; rsB += p2 + p3;
            uint2 pa; pa.x = f2tf(p0); pa.y = f2tf(p1);
            *(uint2*)&Ps[(wr0 + rA)     * PLD + nt * 8 + kq * 2] = pa;
            uint2 pb; pb.x = f2tf(p2); pb.y = f2tf(p3);
            *(uint2*)&Ps[(wr0 + rA + 8) * PLD + nt * 8 + kq * 2] = pb;
        }
        rsA += __shfl_xor_sync(0xffffffffu, rsA, 1);
        rsA += __shfl_xor_sync(0xffffffffu, rsA, 2);
        rsB += __shfl_xor_sync(0xffffffffu, rsB, 1);
        rsB += __shfl_xor_sync(0xffffffffu, rsB, 2);
        lA = lA * cA + rsA; lB = lB * cB + rsB;
        #pragma unroll
        for (int nt2 = 0; nt2 < 16; nt2++) {
            of[nt2][0] *= cA; of[nt2][1] *= cA;
            of[nt2][2] *= cB; of[nt2][3] *= cB;
        }
        __syncwarp();

        #pragma unroll
        for (int ks = 0; ks < 8; ks++) {
            uint32_t aa[4];
            aa[0] = Ps[(wr0 + rA)     * PLD + ks * 8 + kq];
            aa[1] = Ps[(wr0 + rA + 8) * PLD + ks * 8 + kq];
            aa[2] = Ps[(wr0 + rA)     * PLD + ks * 8 + 4 + kq];
            aa[3] = Ps[(wr0 + rA + 8) * PLD + ks * 8 + 4 + kq];
            #pragma unroll
            for (int nt2 = 0; nt2 < 16; nt2++) {
                uint32_t bb[2];
                bb[0] = Vt[(nt2 * 8 + rA) * PLD + ks * 8 + kq];
                bb[1] = Vt[(nt2 * 8 + rA) * PLD + ks * 8 + 4 + kq];
                MMA_TF32(of[nt2], aa, bb);
            }
        }
    }

    const float iA = 1.f / lA, iB = 1.f / lB;
    const int rowA = q0 + wr0 + rA, rowB = rowA + 8;
    #pragma unroll
    for (int nt2 = 0; nt2 < 16; nt2++) {
        int col = h * HEAD + nt2 * 8 + kq * 2;
        float2 va; va.x = of[nt2][0] * iA; va.y = of[nt2][1] * iA;
        *(float2*)&O[(size_t)rowA * QH + col] = va;
        float2 vb; vb.x = of[nt2][2] * iB; vb.y = of[nt2][3] * iB;
        *(float2*)&O[(size_t)rowB * QH + col] = vb;
    }
}

// ----------------------------------------------------------------------------
// RMSNorm over D=2048, one block per row
// ----------------------------------------------------------------------------
__global__ __launch_bounds__(256) void rmsnorm_kernel(
    const float* __restrict__ x, const float* __restrict__ w, float* __restrict__ out)
{
    const int t = blockIdx.x, tid = threadIdx.x;
    const float4* xr = (const float4*)(x + (size_t)t*D_MODEL);
    float4 a = xr[tid], b = xr[tid+256];
    float ss = a.x*a.x + a.y*a.y + a.z*a.z + a.w*a.w
             + b.x*b.x + b.y*b.y + b.z*b.z + b.w*b.w;
    #pragma unroll
    for (int off=16; off>0; off>>=1) ss += __shfl_xor_sync(0xffffffffu, ss, off);
    __shared__ float red[8];
    if ((tid&31)==0) red[tid>>5] = ss;
    __syncthreads();
    float tot = red[0]+red[1]+red[2]+red[3]+red[4]+red[5]+red[6]+red[7];
    float inv = rsqrtf(tot/(float)D_MODEL + EPS);
    const float4* wr = (const float4*)w;
    float4 wa = wr[tid], wb = wr[tid+256];
    float4* orow = (float4*)(out + (size_t)t*D_MODEL);
    orow[tid]     = make_float4(a.x*inv*wa.x, a.y*inv*wa.y, a.z*inv*wa.z, a.w*inv*wa.w);
    orow[tid+256] = make_float4(b.x*inv*wb.x, b.y*inv*wb.y, b.z*inv*wb.z, b.w*inv*wb.w);
}

// ----------------------------------------------------------------------------
// Per-head RMSNorm (H=128) + RoPE. One block (128 thr) per row.
// ----------------------------------------------------------------------------
__global__ __launch_bounds__(128) void qknorm_rope(
    float* __restrict__ x, const float* __restrict__ nw,
    const float* __restrict__ cosb, const float* __restrict__ sinb, int NH)
{
    const int row = blockIdx.x;
    const int t = row / NH;
    const int tid = threadIdx.x;
    float v = x[(size_t)row*HEAD + tid];
    float ss = v*v;
    #pragma unroll
    for (int off=16; off>0; off>>=1) ss += __shfl_xor_sync(0xffffffffu, ss, off);
    __shared__ float red[4];
    __shared__ float xs[HEAD];
    if ((tid&31)==0) red[tid>>5] = ss;
    __syncthreads();
    float tot = red[0]+red[1]+red[2]+red[3];
    float inv = rsqrtf(tot/(float)HEAD + EPS);
    float xn = v*inv*nw[tid];
    xs[tid] = xn;
    __syncthreads();
    float other = xs[tid^64];
    float c = cosb[(size_t)t*HEAD + tid];
    float s = sinb[(size_t)t*HEAD + tid];
    float outv = (tid < 64) ? (xn*c - other*s) : (xn*c + other*s);
    x[(size_t)row*HEAD + tid] = outv;
}

// ----------------------------------------------------------------------------
// MoE router + permutation machinery
// ----------------------------------------------------------------------------
__global__ __launch_bounds__(128) void router_kernel(
    const float* __restrict__ h2, const float* __restrict__ gw)
{
    const int t = blockIdx.x, tid = threadIdx.x;
    const int e = tid & 15, c = tid >> 4;
    const float* x = h2 + (size_t)t*D_MODEL;
    float acc = 0.f;
    for (int d = c*256; d < c*256+256; d++)
        acc += x[d]*gw[d*N_EXP + e];
    __shared__ float part[8][16];
    part[c][e] = acc;
    __syncthreads();
    if (tid == 0) {
        float lg[16];
        for (int ee=0; ee<16; ee++) {
            float s = 0.f;
            for (int cc=0; cc<8; cc++) s += part[cc][ee];
            lg[ee] = s;
        }
        float mx = lg[0];
        for (int ee=1; ee<16; ee++) mx = fmaxf(mx, lg[ee]);
        float pb[16]; float sum = 0.f;
        for (int ee=0; ee<16; ee++) { pb[ee] = expf(lg[ee]-mx); sum += pb[ee]; }
        float isum = 1.f/sum;
        for (int ee=0; ee<16; ee++) pb[ee] *= isum;
        bool used[16] = {};
        int idx4[4]; float w4[4]; float wsum = 0.f;
        for (int s4=0; s4<4; s4++) {
            int bi = -1; float bv = -1.f;
            for (int ee=0; ee<16; ee++)
                if (!used[ee] && pb[ee] > bv) { bv = pb[ee]; bi = ee; }
            used[bi] = true; idx4[s4] = bi; w4[s4] = bv; wsum += bv;
        }
        for (int s4=0; s4<4; s4++) {
            g_topidx[t*4+s4] = idx4[s4];
            g_topw[t*4+s4]   = w4[s4]/wsum;
            atomicAdd(&g_cnt[idx4[s4]], 1);
        }
    }
}

__global__ void zero_kernel() {
    if (threadIdx.x < N_EXP) g_cnt[threadIdx.x] = 0;
}
__global__ void offsets_kernel() {
    if (threadIdx.x == 0) {
        int acc = 0;
        for (int e=0; e<N_EXP; e++) { g_off[e] = acc; acc += g_cnt[e]; g_cursor[e] = 0; }
        g_off[N_EXP] = acc;
    }
}
__global__ __launch_bounds__(256) void scatter_kernel() {
    int idx = blockIdx.x*blockDim.x + threadIdx.x;
    if (idx >= SLOTS) return;
    int t = idx >> 2;
    int e = g_topidx[idx];
    int p = atomicAdd(&g_cursor[e], 1);
    int r = g_off[e] + p;
    g_tokperm[r] = t;
    g_slotrow[idx] = r;
}

// silu over float4
__global__ __launch_bounds__(256) void silu_kernel() {
    int idx = blockIdx.x*blockDim.x + threadIdx.x;
    if (idx >= SLOTS*256) return;
    int r = idx >> 8, f4 = idx & 255;
    const float4* gu = (const float4*)(g_gu + (size_t)r*2048);
    float4 g4 = gu[f4];
    float4 u4 = gu[256 + f4];
    float4 o;
    o.x = u4.x * (g4.x / (1.f + __expf(-g4.x)));
    o.y = u4.y * (g4.y / (1.f + __expf(-g4.y)));
    o.z = u4.z * (g4.z / (1.f + __expf(-g4.z)));
    o.w = u4.w * (g4.w / (1.f + __expf(-g4.w)));
    ((float4*)(g_gated + (size_t)r*F_FF))[f4] = o;
}

// combine over float4
__global__ __launch_bounds__(256) void combine_kernel(float* __restrict__ out)
{
    int idx = blockIdx.x*blockDim.x + threadIdx.x;
    if (idx >= T_TOK*512) return;
    int t = idx >> 9, d4 = idx & 511;
    float4 acc = ((const float4*)(g_resid2 + (size_t)t*2048))[d4];
    #pragma unroll
    for (int s=0; s<4; s++) {
        int row = g_slotrow[t*4+s];
        float wgt = g_topw[t*4+s];
        float4 v = ((const float4*)(g_downo + (size_t)row*2048))[d4];
        acc.x += wgt*v.x; acc.y += wgt*v.y; acc.z += wgt*v.z; acc.w += wgt*v.w;
    }
    ((float4*)out)[idx] = acc;
}

// ----------------------------------------------------------------------------
// Launcher
// ----------------------------------------------------------------------------
extern "C" void kernel_launch(void* const* d_in, const int* in_sizes, int n_in,
                              void* d_out, int out_size)
{
    const float* hidden = (const float*)d_in[0];
    const float* cosb   = (const float*)d_in[1];
    const float* sinb   = (const float*)d_in[2];
    // d_in[3] attention_mask: exactly causal; applied analytically in-kernel
    const float* iln    = (const float*)d_in[4];
    const float* pln    = (const float*)d_in[5];
    const float* qw     = (const float*)d_in[6];
    const float* kw     = (const float*)d_in[7];
    const float* vw     = (const float*)d_in[8];
    const float* ow     = (const float*)d_in[9];
    const float* qnw    = (const float*)d_in[10];
    const float* knw    = (const float*)d_in[11];
    const float* gw     = (const float*)d_in[12];
    const float* guw    = (const float*)d_in[13];
    const float* dww    = (const float*)d_in[14];
    float* out = (float*)d_out;

    cudaFuncSetAttribute(attn_mma,     cudaFuncAttributeMaxDynamicSharedMemorySize, ATTN_SMEM);
    cudaFuncSetAttribute(mma_gemm_qkv, cudaFuncAttributeMaxDynamicSharedMemorySize, GEMM_SMEM);
    cudaFuncSetAttribute(mma_gemm<0>,  cudaFuncAttributeMaxDynamicSharedMemorySize, GEMM_SMEM);
    cudaFuncSetAttribute(mma_gemm<1>,  cudaFuncAttributeMaxDynamicSharedMemorySize, GEMM_SMEM);
    cudaFuncSetAttribute(mma_gemm<2>,  cudaFuncAttributeMaxDynamicSharedMemorySize, GEMM_SMEM);

    void* p;
    cudaGetSymbolAddress(&p, g_hnorm);  float* hnorm  = (float*)p;
    cudaGetSymbolAddress(&p, g_q);      float* qbuf   = (float*)p;
    cudaGetSymbolAddress(&p, g_k);      float* kbuf   = (float*)p;
    cudaGetSymbolAddress(&p, g_v);      float* vbuf   = (float*)p;
    cudaGetSymbolAddress(&p, g_attn);   float* abuf   = (float*)p;
    cudaGetSymbolAddress(&p, g_resid2); float* resid2 = (float*)p;
    cudaGetSymbolAddress(&p, g_h2);     float* h2buf  = (float*)p;
    cudaGetSymbolAddress(&p, g_gu);     float* gubuf  = (float*)p;
    cudaGetSymbolAddress(&p, g_gated);  float* gtbuf  = (float*)p;
    cudaGetSymbolAddress(&p, g_downo);  float* dobuf  = (float*)p;

    // 1) input RMSNorm
    rmsnorm_kernel<<<T_TOK, 256>>>(hidden, iln, hnorm);
    // 2) fused QKV projection (tf32 mma, cp.async pipeline)
    mma_gemm_qkv<<<dim3(24, T_TOK/128), 256, GEMM_SMEM>>>(hnorm, qw, kw, vw, qbuf, kbuf, vbuf);
    // 3) per-head norm + RoPE
    qknorm_rope<<<T_TOK*N_Q,  128>>>(qbuf, qnw, cosb, sinb, N_Q);
    qknorm_rope<<<T_TOK*N_KV, 128>>>(kbuf, knw, cosb, sinb, N_KV);
    // 4) causal GQA attention (tf32 mma)
    attn_mma<<<dim3(T_TOK/128, N_Q), 256, ATTN_SMEM>>>(qbuf, kbuf, vbuf, abuf);
    // 5) O projection + residual add
    mma_gemm<0><<<dim3(D_MODEL/128, T_TOK/128), 256, GEMM_SMEM>>>(abuf, ow, D_MODEL, hidden, resid2, D_MODEL, QH);
    // 6) post RMSNorm
    rmsnorm_kernel<<<T_TOK, 256>>>(resid2, pln, h2buf);
    // 7) MoE routing + expert permutation
    zero_kernel<<<1, 32>>>();
    router_kernel<<<T_TOK, 128>>>(h2buf, gw);
    offsets_kernel<<<1, 1>>>();
    scatter_kernel<<<SLOTS/256, 256>>>();
    // 8) sparse expert GEMMs (tf32 mma, cp.async pipeline)
    mma_gemm<1><<<dim3(2048/128, T_TOK/128, N_EXP), 256, GEMM_SMEM>>>(h2buf, guw, 2048, nullptr, gubuf, 2048, 2048);
    silu_kernel<<<(SLOTS*256)/256, 256>>>();
    mma_gemm<2><<<dim3(D_MODEL/128, T_TOK/128, N_EXP), 256, GEMM_SMEM>>>(gtbuf, dww, 2048, nullptr, dobuf, 2048, 1024);
    // 9) weighted combine + residual
    combine_kernel<<<(T_TOK*512)/256, 256>>>(out);
}

// round 10
// speedup vs baseline: 7.2483x; 1.0255x over previous
#include <cuda_runtime.h>
#include <cuda_bf16.h>
#include <math.h>
#include <stdint.h>

// ----------------------------------------------------------------------------
// Problem constants
// ----------------------------------------------------------------------------
#define T_TOK 2048
#define D_MODEL 2048
#define N_Q 16
#define N_KV 4
#define HEAD 128
#define QH (N_Q*HEAD)      // 2048
#define KVH (N_KV*HEAD)    // 512
#define N_EXP 16
#define F_FF 1024
#define TOPK 4
#define SLOTS (T_TOK*TOPK) // 8192
#define EPS 1e-6f

// ----------------------------------------------------------------------------
// Scratch (device globals; no dynamic allocation allowed)
// ----------------------------------------------------------------------------
__device__ float g_hnorm[T_TOK*D_MODEL];
__device__ float g_q[T_TOK*QH];
__device__ float g_k[T_TOK*KVH];
__device__ float g_v[T_TOK*KVH];
__device__ float g_attn[T_TOK*QH];
__device__ float g_resid2[T_TOK*D_MODEL];
__device__ float g_h2[T_TOK*D_MODEL];
__device__ float g_topw[SLOTS];
__device__ int   g_topidx[SLOTS];
__device__ int   g_cnt[N_EXP];
__device__ int   g_off[N_EXP+1];
__device__ int   g_cursor[N_EXP];
__device__ int   g_tokperm[SLOTS];
__device__ int   g_slotrow[SLOTS];
__device__ float g_gu[(size_t)SLOTS*2048];
__device__ float g_gated[(size_t)SLOTS*F_FF];
__device__ float g_downo[(size_t)SLOTS*D_MODEL];

// ----------------------------------------------------------------------------
// helpers (baseline PTX; compute_103-safe, no 'a'-features)
// ----------------------------------------------------------------------------
__device__ __forceinline__ uint32_t f2tf(float f) {
    uint32_t u;
    asm("cvt.rna.tf32.f32 %0, %1;" : "=r"(u) : "f"(f));
    return u;
}
__device__ __forceinline__ uint32_t smem_u32(const void* p) {
    uint32_t a;
    asm("{ .reg .u64 t; cvta.to.shared.u64 t, %1; cvt.u32.u64 %0, t; }"
        : "=r"(a) : "l"(p));
    return a;
}
__device__ __forceinline__ void cp16(uint32_t dst, const void* src) {
    asm volatile("cp.async.cg.shared.global [%0], [%1], 16;" :: "r"(dst), "l"(src));
}

#define MMA_TF32(cc, aa, bb) \
    asm volatile("mma.sync.aligned.m16n8k8.row.col.f32.tf32.tf32.f32 " \
        "{%0,%1,%2,%3}, {%4,%5,%6,%7}, {%8,%9}, {%0,%1,%2,%3};" \
        : "+f"(cc[0]), "+f"(cc[1]), "+f"(cc[2]), "+f"(cc[3]) \
        : "r"(aa[0]), "r"(aa[1]), "r"(aa[2]), "r"(aa[3]), "r"(bb[0]), "r"(bb[1]))

// A tile smem: [row 0..127][k 0..31], float idx:
#define SWZA(r, c) ((r)*32 + (((((c)>>2) ^ ((r)&7))) << 2) + ((c)&3))
// B tile smem: [k 0..31][n 0..127], float idx:
#define SWZB(k, n) ((k)*128 + (((((n)>>2) ^ (((k)&3)<<1))) << 2) + ((n)&3))

// ----------------------------------------------------------------------------
// tf32 tensor-core GEMM: block tile 128x128x32, 256 thr, 8 warps.
// 3-stage cp.async pipeline, compile-time stage rotation, K as template param.
// ----------------------------------------------------------------------------
#define GBM 128
#define GBN 128
#define GBK 32
#define NSTG 3
#define GEMM_SMEM (NSTG*32768)

#define ISSUE_S(S, IT) do {                                                    \
    const int k0_ = (IT)*GBK;                                                  \
    uint32_t ab_ = smemU + (uint32_t)(S)*32768u;                               \
    uint32_t bb_ = ab_ + 16384u;                                               \
    _Pragma("unroll")                                                          \
    for (int i_=0;i_<4;i_++) cp16(ab_ + aoffB[i_], arp[i_] + k0_);             \
    _Pragma("unroll")                                                          \
    for (int i_=0;i_<4;i_++) cp16(bb_ + boffB[i_], brp[i_] + (size_t)k0_*ldb); \
    asm volatile("cp.async.commit_group;" ::: "memory");                       \
} while(0)

#define COMPUTE_S(S) do {                                                      \
    const uint32_t* as_ = smu + (S)*8192;                                      \
    const uint32_t* bs_ = as_ + 4096;                                          \
    _Pragma("unroll")                                                          \
    for (int ks_=0; ks_<4; ks_++) {                                            \
        const int k0_ = ks_*8;                                                 \
        uint32_t af[4][4], bf[4][2];                                           \
        _Pragma("unroll")                                                      \
        for (int mt_=0; mt_<4; mt_++) {                                        \
            int r_ = wm + mt_*16 + (lane>>2);                                  \
            af[mt_][0] = as_[SWZA(r_,   k0_+(lane&3))];                        \
            af[mt_][1] = as_[SWZA(r_+8, k0_+(lane&3))];                        \
            af[mt_][2] = as_[SWZA(r_,   k0_+4+(lane&3))];                      \
            af[mt_][3] = as_[SWZA(r_+8, k0_+4+(lane&3))];                      \
        }                                                                      \
        _Pragma("unroll")                                                      \
        for (int nt_=0; nt_<4; nt_++) {                                        \
            int n_ = wn + nt_*8 + (lane>>2);                                   \
            bf[nt_][0] = bs_[SWZB(k0_+(lane&3),   n_)];                        \
            bf[nt_][1] = bs_[SWZB(k0_+4+(lane&3), n_)];                        \
        }                                                                      \
        _Pragma("unroll")                                                      \
        for (int mt_=0; mt_<4; mt_++)                                          \
            _Pragma("unroll")                                                  \
            for (int nt_=0; nt_<4; nt_++)                                      \
                MMA_TF32(c[mt_][nt_], af[mt_], bf[nt_]);                       \
    }                                                                          \
} while(0)

#define GEMM_BODY(S) do {                                                      \
    asm volatile("cp.async.wait_group 1;" ::: "memory");                       \
    __syncthreads();                                                           \
    if (itv + 2 < nIter) { ISSUE_S(((S)+2)%NSTG, itv+2); }                     \
    else { asm volatile("cp.async.commit_group;" ::: "memory"); }              \
    COMPUTE_S(S);                                                              \
    itv++;                                                                     \
} while(0)

#define GEMM_PIPELINE()                                                        \
    const int nIter = K / GBK;                                                 \
    ISSUE_S(0, 0);                                                             \
    ISSUE_S(1, 1);                                                             \
    int itv = 0;                                                               \
    while (itv + 3 <= nIter) { GEMM_BODY(0); GEMM_BODY(1); GEMM_BODY(2); }     \
    if (itv < nIter) { GEMM_BODY(0); }                                         \
    if (itv < nIter) { GEMM_BODY(1); }

// Generic GEMM. MODE 0: plain.  MODE 1: MoE gate_up.  MODE 2: MoE down.
template<int MODE, int K>
__global__ __launch_bounds__(256, 2)
void mma_gemm(const float* __restrict__ A, const float* __restrict__ B, int ldb,
              const float* __restrict__ Cadd, float* __restrict__ C, int ldc)
{
    extern __shared__ uint32_t smu[];
    const uint32_t smemU = smem_u32(smu);

    const int tid  = threadIdx.x;
    const int lane = tid & 31;
    const int w    = tid >> 5;
    const int wm   = (w & 1) * 64;
    const int wn   = (w >> 1) * 32;
    const int bn   = blockIdx.x * GBN;
    const int m0   = blockIdx.y * GBM;

    int cnt_rows = GBM;
    int base = 0;
    size_t cBase;
    const float* Bsrc = B;
    if (MODE == 0) {
        cBase = (size_t)m0 * ldc;
    } else {
        const int e = blockIdx.z;
        const int cnt = g_cnt[e];
        if (m0 >= cnt) return;
        base = g_off[e];
        cnt_rows = min(GBM, cnt - m0);
        Bsrc = B + (size_t)e * (size_t)K * (size_t)ldb;
        cBase = (size_t)(base + m0) * ldc;
    }

    const int ac4 = tid & 7;
    const float* arp[4];
    uint32_t aoffB[4];
    #pragma unroll
    for (int i = 0; i < 4; i++) {
        int row = (tid >> 3) + i * 32;
        int rl = min(row, cnt_rows - 1);
        size_t gr;
        if (MODE == 0)      gr = (size_t)(m0 + row);
        else if (MODE == 1) gr = (size_t)g_tokperm[base + m0 + rl];
        else                gr = (size_t)(base + m0 + rl);
        arp[i] = A + gr * (size_t)K + ac4 * 4;
        aoffB[i] = 4u * (uint32_t)(row * 32 + ((ac4 ^ (row & 7)) << 2));
    }
    const int bk  = tid >> 5;
    const int bn4 = tid & 31;
    const float* brp[4];
    uint32_t boffB[4];
    #pragma unroll
    for (int i = 0; i < 4; i++) {
        int kk = bk + i * 8;
        brp[i] = Bsrc + (size_t)kk * ldb + bn + bn4 * 4;
        boffB[i] = 4u * (uint32_t)(kk * 128 + ((bn4 ^ ((kk & 3) << 1)) << 2));
    }

    float c[4][4][4] = {};
    GEMM_PIPELINE();

    #pragma unroll
    for (int mt = 0; mt < 4; mt++) {
        #pragma unroll
        for (int h = 0; h < 2; h++) {
            int r = wm + mt * 16 + (lane >> 2) + h * 8;
            if (r < cnt_rows) {
                float* dst = C + cBase + (size_t)r * ldc + bn;
                const float* ad = Cadd ? (Cadd + cBase + (size_t)r * ldc + bn)
                                       : (const float*)0;
                #pragma unroll
                for (int nt = 0; nt < 4; nt++) {
                    int col = wn + nt * 8 + ((lane & 3) << 1);
                    float v0 = c[mt][nt][h * 2 + 0];
                    float v1 = c[mt][nt][h * 2 + 1];
                    if (ad) { v0 += ad[col]; v1 += ad[col + 1]; }
                    dst[col]     = v0;
                    dst[col + 1] = v1;
                }
            }
        }
    }
}

// ----------------------------------------------------------------------------
// Fused QKV GEMM: q (2048 cols) + k (512) + v (512) in one launch.
// ----------------------------------------------------------------------------
__global__ __launch_bounds__(256, 2)
void mma_gemm_qkv(const float* __restrict__ A,
                  const float* __restrict__ Bq, const float* __restrict__ Bk2,
                  const float* __restrict__ Bv,
                  float* __restrict__ Cq, float* __restrict__ Ck,
                  float* __restrict__ Cv)
{
    extern __shared__ uint32_t smu[];
    const uint32_t smemU = smem_u32(smu);

    const int tid  = threadIdx.x;
    const int lane = tid & 31;
    const int w    = tid >> 5;
    const int wm   = (w & 1) * 64;
    const int wn   = (w >> 1) * 32;
    const int m0   = blockIdx.y * GBM;
    const int bnG  = blockIdx.x * GBN;

    const float* Bsrc;
    float* C;
    int ldb, bn;
    if (bnG < 2048)      { Bsrc = Bq;  C = Cq; ldb = 2048; bn = bnG; }
    else if (bnG < 2560) { Bsrc = Bk2; C = Ck; ldb = 512;  bn = bnG - 2048; }
    else                 { Bsrc = Bv;  C = Cv; ldb = 512;  bn = bnG - 2560; }
    const int K = 2048;

    const int ac4 = tid & 7;
    const float* arp[4];
    uint32_t aoffB[4];
    #pragma unroll
    for (int i = 0; i < 4; i++) {
        int row = (tid >> 3) + i * 32;
        arp[i] = A + (size_t)(m0 + row) * K + ac4 * 4;
        aoffB[i] = 4u * (uint32_t)(row * 32 + ((ac4 ^ (row & 7)) << 2));
    }
    const int bk  = tid >> 5;
    const int bn4 = tid & 31;
    const float* brp[4];
    uint32_t boffB[4];
    #pragma unroll
    for (int i = 0; i < 4; i++) {
        int kk = bk + i * 8;
        brp[i] = Bsrc + (size_t)kk * ldb + bn + bn4 * 4;
        boffB[i] = 4u * (uint32_t)(kk * 128 + ((bn4 ^ ((kk & 3) << 1)) << 2));
    }

    float c[4][4][4] = {};
    GEMM_PIPELINE();

    #pragma unroll
    for (int mt = 0; mt < 4; mt++) {
        #pragma unroll
        for (int h = 0; h < 2; h++) {
            int r = wm + mt * 16 + (lane >> 2) + h * 8;
            float* dst = C + (size_t)(m0 + r) * ldb + bn;
            #pragma unroll
            for (int nt = 0; nt < 4; nt++) {
                int col = wn + nt * 8 + ((lane & 3) << 1);
                dst[col]     = c[mt][nt][h * 2 + 0];
                dst[col + 1] = c[mt][nt][h * 2 + 1];
            }
        }
    }
}

// ----------------------------------------------------------------------------
// tf32 mma flash attention v2.  Block = (q-tile 128, head). 256 thr, 8 warps.
// - qb reversed for load balance (heaviest blocks first)
// - Q + double-buffered K/V staged via cp.async (raw fp32 bits -> tf32 trunc)
// - V kept [j][d] (no transpose); PV B-frag reads conflict-free w/ 132 pad
// - P fragments passed S->PV via quad shuffles (no Ps smem)
// smem: Qs 128x132 + 2 stages x (K 64x132 + V 64x132) = 202752 B
// ----------------------------------------------------------------------------
#define QLD 132
#define ATTN_SMEM ((128*QLD + 4*64*QLD)*4)

#define AISSUE(S, KB) do {                                                     \
    const int kk0_ = (KB)*64;                                                  \
    uint32_t kb_ = smemU + (uint32_t)(128*QLD + (S)*128*QLD)*4u;               \
    uint32_t vb_ = kb_ + (uint32_t)(64*QLD)*4u;                                \
    _Pragma("unroll")                                                          \
    for (int i_=0;i_<8;i_++) {                                                 \
        int idx_ = tid + i_*256;                                               \
        int r_ = idx_>>5, c_ = idx_&31;                                        \
        cp16(kb_ + (uint32_t)(r_*QLD + c_*4)*4u,                               \
             Kg + (size_t)(kk0_+r_)*KVH + kvh*HEAD + c_*4);                    \
        cp16(vb_ + (uint32_t)(r_*QLD + c_*4)*4u,                               \
             Vg + (size_t)(kk0_+r_)*KVH + kvh*HEAD + c_*4);                    \
    }                                                                          \
    asm volatile("cp.async.commit_group;" ::: "memory");                       \
} while(0)

__global__ __launch_bounds__(256) void attn_mma(
    const float* __restrict__ Q, const float* __restrict__ Kg,
    const float* __restrict__ Vg, float* __restrict__ O)
{
    extern __shared__ uint32_t smw[];
    const uint32_t smemU = smem_u32(smw);
    const uint32_t* Qs = smw;                 // [128][132]

    const int h = blockIdx.y, kvh = h >> 2;
    const int qb = (int)gridDim.x - 1 - (int)blockIdx.x;   // heavy blocks first
    const int q0 = qb * 128;
    const int tid = threadIdx.x, lane = tid & 31, w = tid >> 5;
    const int wr0 = w * 16;
    const int rA = lane >> 2;      // 0..7
    const int kq = lane & 3;       // 0..3
    const float scale = 0.08838834764831845f; // 128^-0.5

    // Stage Q (raw bits) + first K/V tile; all in cp.async group 0
    #pragma unroll
    for (int i = 0; i < 16; i++) {
        int idx = tid + i * 256;
        int r = idx >> 5, c = idx & 31;
        cp16(smemU + (uint32_t)(r * QLD + c * 4) * 4u,
             Q + (size_t)(q0 + r) * QH + h * HEAD + c * 4);
    }
    AISSUE(0, 0);

    float mA = -1e30f, mB = -1e30f, lA = 0.f, lB = 0.f;
    float of[16][4];
    #pragma unroll
    for (int i = 0; i < 16; i++)
        { of[i][0] = 0.f; of[i][1] = 0.f; of[i][2] = 0.f; of[i][3] = 0.f; }

    const int nkb = 2 * qb + 2;
    for (int kb = 0; kb < nkb; kb++) {
        const int k0 = kb * 64;
        asm volatile("cp.async.wait_group 0;" ::: "memory");
        __syncthreads();
        if (kb + 1 < nkb) AISSUE((kb + 1) & 1, kb + 1);

        const uint32_t* KsP = smw + 128*QLD + (kb & 1) * 128*QLD;
        const uint32_t* VsP = KsP + 64*QLD;

        if (q0 + wr0 + 15 >= k0) {
            // S = Q K^T  (warp: 16 rows x 64 cols)
            float sf[8][4];
            #pragma unroll
            for (int nt = 0; nt < 8; nt++)
                { sf[nt][0]=0.f; sf[nt][1]=0.f; sf[nt][2]=0.f; sf[nt][3]=0.f; }
            #pragma unroll
            for (int ks = 0; ks < 16; ks++) {
                uint32_t aa[4];
                aa[0] = Qs[(wr0 + rA)     * QLD + ks * 8 + kq];
                aa[1] = Qs[(wr0 + rA + 8) * QLD + ks * 8 + kq];
                aa[2] = Qs[(wr0 + rA)     * QLD + ks * 8 + 4 + kq];
                aa[3] = Qs[(wr0 + rA + 8) * QLD + ks * 8 + 4 + kq];
                #pragma unroll
                for (int nt = 0; nt < 8; nt++) {
                    uint32_t bb[2];
                    bb[0] = KsP[(nt * 8 + rA) * QLD + ks * 8 + kq];
                    bb[1] = KsP[(nt * 8 + rA) * QLD + ks * 8 + 4 + kq];
                    MMA_TF32(sf[nt], aa, bb);
                }
            }
            // scale (applied post-MMA so Q could be raw-copied)
            #pragma unroll
            for (int nt = 0; nt < 8; nt++) {
                sf[nt][0] *= scale; sf[nt][1] *= scale;
                sf[nt][2] *= scale; sf[nt][3] *= scale;
            }

            // mask + online softmax
            const int rowA = q0 + wr0 + rA;
            const int rowB = rowA + 8;
            if (kb >= 2 * qb) {
                #pragma unroll
                for (int nt = 0; nt < 8; nt++) {
                    #pragma unroll
                    for (int u = 0; u < 2; u++) {
                        int col = k0 + nt * 8 + kq * 2 + u;
                        if (col > rowA) sf[nt][u]     = -1e30f;
                        if (col > rowB) sf[nt][2 + u] = -1e30f;
                    }
                }
            }
            float mxA = -1e30f, mxB = -1e30f;
            #pragma unroll
            for (int nt = 0; nt < 8; nt++) {
                mxA = fmaxf(mxA, fmaxf(sf[nt][0], sf[nt][1]));
                mxB = fmaxf(mxB, fmaxf(sf[nt][2], sf[nt][3]));
            }
            mxA = fmaxf(mxA, __shfl_xor_sync(0xffffffffu, mxA, 1));
            mxA = fmaxf(mxA, __shfl_xor_sync(0xffffffffu, mxA, 2));
            mxB = fmaxf(mxB, __shfl_xor_sync(0xffffffffu, mxB, 1));
            mxB = fmaxf(mxB, __shfl_xor_sync(0xffffffffu, mxB, 2));
            float mnA = fmaxf(mA, mxA), mnB = fmaxf(mB, mxB);
            float cA = __expf(mA - mnA), cB = __expf(mB - mnB);
            mA = mnA; mB = mnB;
            float rsA = 0.f, rsB = 0.f;
            #pragma unroll
            for (int nt = 0; nt < 8; nt++) {
                sf[nt][0] = __expf(sf[nt][0] - mnA);
                sf[nt][1] = __expf(sf[nt][1] - mnA);
                sf[nt][2] = __expf(sf[nt][2] - mnB);
                sf[nt][3] = __expf(sf[nt][3] - mnB);
                rsA += sf[nt][0] + sf[nt][1];
                rsB += sf[nt][2] + sf[nt][3];
            }
            rsA += __shfl_xor_sync(0xffffffffu, rsA, 1);
            rsA += __shfl_xor_sync(0xffffffffu, rsA, 2);
            rsB += __shfl_xor_sync(0xffffffffu, rsB, 1);
            rsB += __shfl_xor_sync(0xffffffffu, rsB, 2);
            lA = lA * cA + rsA; lB = lB * cB + rsB;
            #pragma unroll
            for (int nt2 = 0; nt2 < 16; nt2++) {
                of[nt2][0] *= cA; of[nt2][1] *= cA;
                of[nt2][2] *= cB; of[nt2][3] *= cB;
            }

            // O += P V.  P fragments via quad shuffles (no smem round-trip).
            const int src = (rA << 2) + (kq >> 1);
            const bool sel = kq & 1;
            #pragma unroll
            for (int ks = 0; ks < 8; ks++) {
                float t00 = __shfl_sync(0xffffffffu, sf[ks][0], src);
                float t01 = __shfl_sync(0xffffffffu, sf[ks][1], src);
                float t10 = __shfl_sync(0xffffffffu, sf[ks][2], src);
                float t11 = __shfl_sync(0xffffffffu, sf[ks][3], src);
                float t20 = __shfl_sync(0xffffffffu, sf[ks][0], src + 2);
                float t21 = __shfl_sync(0xffffffffu, sf[ks][1], src + 2);
                float t30 = __shfl_sync(0xffffffffu, sf[ks][2], src + 2);
                float t31 = __shfl_sync(0xffffffffu, sf[ks][3], src + 2);
                uint32_t aa[4];
                aa[0] = f2tf(sel ? t01 : t00);
                aa[1] = f2tf(sel ? t11 : t10);
                aa[2] = f2tf(sel ? t21 : t20);
                aa[3] = f2tf(sel ? t31 : t30);
                #pragma unroll
                for (int nt2 = 0; nt2 < 16; nt2++) {
                    uint32_t bb[2];
                    bb[0] = VsP[(ks * 8 + kq)     * QLD + nt2 * 8 + rA];
                    bb[1] = VsP[(ks * 8 + 4 + kq) * QLD + nt2 * 8 + rA];
                    MMA_TF32(of[nt2], aa, bb);
                }
            }
        }
    }

    const float iA = 1.f / lA, iB = 1.f / lB;
    const int rowA = q0 + wr0 + rA, rowB = rowA + 8;
    #pragma unroll
    for (int nt2 = 0; nt2 < 16; nt2++) {
        int col = h * HEAD + nt2 * 8 + kq * 2;
        float2 va; va.x = of[nt2][0] * iA; va.y = of[nt2][1] * iA;
        *(float2*)&O[(size_t)rowA * QH + col] = va;
        float2 vb; vb.x = of[nt2][2] * iB; vb.y = of[nt2][3] * iB;
        *(float2*)&O[(size_t)rowB * QH + col] = vb;
    }
}

// ----------------------------------------------------------------------------
// RMSNorm over D=2048, one block per row
// ----------------------------------------------------------------------------
__global__ __launch_bounds__(256) void rmsnorm_kernel(
    const float* __restrict__ x, const float* __restrict__ w, float* __restrict__ out)
{
    const int t = blockIdx.x, tid = threadIdx.x;
    const float4* xr = (const float4*)(x + (size_t)t*D_MODEL);
    float4 a = xr[tid], b = xr[tid+256];
    float ss = a.x*a.x + a.y*a.y + a.z*a.z + a.w*a.w
             + b.x*b.x + b.y*b.y + b.z*b.z + b.w*b.w;
    #pragma unroll
    for (int off=16; off>0; off>>=1) ss += __shfl_xor_sync(0xffffffffu, ss, off);
    __shared__ float red[8];
    if ((tid&31)==0) red[tid>>5] = ss;
    __syncthreads();
    float tot = red[0]+red[1]+red[2]+red[3]+red[4]+red[5]+red[6]+red[7];
    float inv = rsqrtf(tot/(float)D_MODEL + EPS);
    const float4* wr = (const float4*)w;
    float4 wa = wr[tid], wb = wr[tid+256];
    float4* orow = (float4*)(out + (size_t)t*D_MODEL);
    orow[tid]     = make_float4(a.x*inv*wa.x, a.y*inv*wa.y, a.z*inv*wa.z, a.w*inv*wa.w);
    orow[tid+256] = make_float4(b.x*inv*wb.x, b.y*inv*wb.y, b.z*inv*wb.z, b.w*inv*wb.w);
}

// ----------------------------------------------------------------------------
// Per-head RMSNorm (H=128) + RoPE. One block (128 thr) per row.
// ----------------------------------------------------------------------------
__global__ __launch_bounds__(128) void qknorm_rope(
    float* __restrict__ x, const float* __restrict__ nw,
    const float* __restrict__ cosb, const float* __restrict__ sinb, int NH)
{
    const int row = blockIdx.x;
    const int t = row / NH;
    const int tid = threadIdx.x;
    float v = x[(size_t)row*HEAD + tid];
    float ss = v*v;
    #pragma unroll
    for (int off=16; off>0; off>>=1) ss += __shfl_xor_sync(0xffffffffu, ss, off);
    __shared__ float red[4];
    __shared__ float xs[HEAD];
    if ((tid&31)==0) red[tid>>5] = ss;
    __syncthreads();
    float tot = red[0]+red[1]+red[2]+red[3];
    float inv = rsqrtf(tot/(float)HEAD + EPS);
    float xn = v*inv*nw[tid];
    xs[tid] = xn;
    __syncthreads();
    float other = xs[tid^64];
    float c = cosb[(size_t)t*HEAD + tid];
    float s = sinb[(size_t)t*HEAD + tid];
    float outv = (tid < 64) ? (xn*c - other*s) : (xn*c + other*s);
    x[(size_t)row*HEAD + tid] = outv;
}

// ----------------------------------------------------------------------------
// MoE router + permutation machinery
// ----------------------------------------------------------------------------
__global__ __launch_bounds__(128) void router_kernel(
    const float* __restrict__ h2, const float* __restrict__ gw)
{
    const int t = blockIdx.x, tid = threadIdx.x;
    const int e = tid & 15, c = tid >> 4;
    const float* x = h2 + (size_t)t*D_MODEL;
    float acc = 0.f;
    for (int d = c*256; d < c*256+256; d++)
        acc += x[d]*gw[d*N_EXP + e];
    __shared__ float part[8][16];
    part[c][e] = acc;
    __syncthreads();
    if (tid == 0) {
        float lg[16];
        for (int ee=0; ee<16; ee++) {
            float s = 0.f;
            for (int cc=0; cc<8; cc++) s += part[cc][ee];
            lg[ee] = s;
        }
        float mx = lg[0];
        for (int ee=1; ee<16; ee++) mx = fmaxf(mx, lg[ee]);
        float pb[16]; float sum = 0.f;
        for (int ee=0; ee<16; ee++) { pb[ee] = expf(lg[ee]-mx); sum += pb[ee]; }
        float isum = 1.f/sum;
        for (int ee=0; ee<16; ee++) pb[ee] *= isum;
        bool used[16] = {};
        int idx4[4]; float w4[4]; float wsum = 0.f;
        for (int s4=0; s4<4; s4++) {
            int bi = -1; float bv = -1.f;
            for (int ee=0; ee<16; ee++)
                if (!used[ee] && pb[ee] > bv) { bv = pb[ee]; bi = ee; }
            used[bi] = true; idx4[s4] = bi; w4[s4] = bv; wsum += bv;
        }
        for (int s4=0; s4<4; s4++) {
            g_topidx[t*4+s4] = idx4[s4];
            g_topw[t*4+s4]   = w4[s4]/wsum;
            atomicAdd(&g_cnt[idx4[s4]], 1);
        }
    }
}

__global__ void zero_kernel() {
    if (threadIdx.x < N_EXP) g_cnt[threadIdx.x] = 0;
}
__global__ void offsets_kernel() {
    if (threadIdx.x == 0) {
        int acc = 0;
        for (int e=0; e<N_EXP; e++) { g_off[e] = acc; acc += g_cnt[e]; g_cursor[e] = 0; }
        g_off[N_EXP] = acc;
    }
}
__global__ __launch_bounds__(256) void scatter_kernel() {
    int idx = blockIdx.x*blockDim.x + threadIdx.x;
    if (idx >= SLOTS) return;
    int t = idx >> 2;
    int e = g_topidx[idx];
    int p = atomicAdd(&g_cursor[e], 1);
    int r = g_off[e] + p;
    g_tokperm[r] = t;
    g_slotrow[idx] = r;
}

// silu over float4
__global__ __launch_bounds__(256) void silu_kernel() {
    int idx = blockIdx.x*blockDim.x + threadIdx.x;
    if (idx >= SLOTS*256) return;
    int r = idx >> 8, f4 = idx & 255;
    const float4* gu = (const float4*)(g_gu + (size_t)r*2048);
    float4 g4 = gu[f4];
    float4 u4 = gu[256 + f4];
    float4 o;
    o.x = u4.x * (g4.x / (1.f + __expf(-g4.x)));
    o.y = u4.y * (g4.y / (1.f + __expf(-g4.y)));
    o.z = u4.z * (g4.z / (1.f + __expf(-g4.z)));
    o.w = u4.w * (g4.w / (1.f + __expf(-g4.w)));
    ((float4*)(g_gated + (size_t)r*F_FF))[f4] = o;
}

// combine over float4
__global__ __launch_bounds__(256) void combine_kernel(float* __restrict__ out)
{
    int idx = blockIdx.x*blockDim.x + threadIdx.x;
    if (idx >= T_TOK*512) return;
    int t = idx >> 9, d4 = idx & 511;
    float4 acc = ((const float4*)(g_resid2 + (size_t)t*2048))[d4];
    #pragma unroll
    for (int s=0; s<4; s++) {
        int row = g_slotrow[t*4+s];
        float wgt = g_topw[t*4+s];
        float4 v = ((const float4*)(g_downo + (size_t)row*2048))[d4];
        acc.x += wgt*v.x; acc.y += wgt*v.y; acc.z += wgt*v.z; acc.w += wgt*v.w;
    }
    ((float4*)out)[idx] = acc;
}

// ----------------------------------------------------------------------------
// Launcher
// ----------------------------------------------------------------------------
extern "C" void kernel_launch(void* const* d_in, const int* in_sizes, int n_in,
                              void* d_out, int out_size)
{
    const float* hidden = (const float*)d_in[0];
    const float* cosb   = (const float*)d_in[1];
    const float* sinb   = (const float*)d_in[2];
    // d_in[3] attention_mask: exactly causal; applied analytically in-kernel
    const float* iln    = (const float*)d_in[4];
    const float* pln    = (const float*)d_in[5];
    const float* qw     = (const float*)d_in[6];
    const float* kw     = (const float*)d_in[7];
    const float* vw     = (const float*)d_in[8];
    const float* ow     = (const float*)d_in[9];
    const float* qnw    = (const float*)d_in[10];
    const float* knw    = (const float*)d_in[11];
    const float* gw     = (const float*)d_in[12];
    const float* guw    = (const float*)d_in[13];
    const float* dww    = (const float*)d_in[14];
    float* out = (float*)d_out;

    cudaFuncSetAttribute(attn_mma,     cudaFuncAttributeMaxDynamicSharedMemorySize, ATTN_SMEM);
    cudaFuncSetAttribute(mma_gemm_qkv, cudaFuncAttributeMaxDynamicSharedMemorySize, GEMM_SMEM);
    cudaFuncSetAttribute((const void*)mma_gemm<0,2048>, cudaFuncAttributeMaxDynamicSharedMemorySize, GEMM_SMEM);
    cudaFuncSetAttribute((const void*)mma_gemm<1,2048>, cudaFuncAttributeMaxDynamicSharedMemorySize, GEMM_SMEM);
    cudaFuncSetAttribute((const void*)mma_gemm<2,1024>, cudaFuncAttributeMaxDynamicSharedMemorySize, GEMM_SMEM);

    void* p;
    cudaGetSymbolAddress(&p, g_hnorm);  float* hnorm  = (float*)p;
    cudaGetSymbolAddress(&p, g_q);      float* qbuf   = (float*)p;
    cudaGetSymbolAddress(&p, g_k);      float* kbuf   = (float*)p;
    cudaGetSymbolAddress(&p, g_v);      float* vbuf   = (float*)p;
    cudaGetSymbolAddress(&p, g_attn);   float* abuf   = (float*)p;
    cudaGetSymbolAddress(&p, g_resid2); float* resid2 = (float*)p;
    cudaGetSymbolAddress(&p, g_h2);     float* h2buf  = (float*)p;
    cudaGetSymbolAddress(&p, g_gu);     float* gubuf  = (float*)p;
    cudaGetSymbolAddress(&p, g_gated);  float* gtbuf  = (float*)p;
    cudaGetSymbolAddress(&p, g_downo);  float* dobuf  = (float*)p;

    // 1) input RMSNorm
    rmsnorm_kernel<<<T_TOK, 256>>>(hidden, iln, hnorm);
    // 2) fused QKV projection (tf32 mma, cp.async pipeline)
    mma_gemm_qkv<<<dim3(24, T_TOK/128), 256, GEMM_SMEM>>>(hnorm, qw, kw, vw, qbuf, kbuf, vbuf);
    // 3) per-head norm + RoPE
    qknorm_rope<<<T_TOK*N_Q,  128>>>(qbuf, qnw, cosb, sinb, N_Q);
    qknorm_rope<<<T_TOK*N_KV, 128>>>(kbuf, knw, cosb, sinb, N_KV);
    // 4) causal GQA attention (tf32 mma, pipelined K/V, shfl P)
    attn_mma<<<dim3(T_TOK/128, N_Q), 256, ATTN_SMEM>>>(qbuf, kbuf, vbuf, abuf);
    // 5) O projection + residual add
    mma_gemm<0,2048><<<dim3(D_MODEL/128, T_TOK/128), 256, GEMM_SMEM>>>(abuf, ow, D_MODEL, hidden, resid2, D_MODEL);
    // 6) post RMSNorm
    rmsnorm_kernel<<<T_TOK, 256>>>(resid2, pln, h2buf);
    // 7) MoE routing + expert permutation
    zero_kernel<<<1, 32>>>();
    router_kernel<<<T_TOK, 128>>>(h2buf, gw);
    offsets_kernel<<<1, 1>>>();
    scatter_kernel<<<SLOTS/256, 256>>>();
    // 8) sparse expert GEMMs (tf32 mma, cp.async pipeline)
    mma_gemm<1,2048><<<dim3(2048/128, T_TOK/128, N_EXP), 256, GEMM_SMEM>>>(h2buf, guw, 2048, nullptr, gubuf, 2048);
    silu_kernel<<<(SLOTS*256)/256, 256>>>();
    mma_gemm<2,1024><<<dim3(D_MODEL/128, T_TOK/128, N_EXP), 256, GEMM_SMEM>>>(gtbuf, dww, 2048, nullptr, dobuf, 2048);
    // 9) weighted combine + residual
    combine_kernel<<<(T_TOK*512)/256, 256>>>(out);
}